// round 7
// baseline (speedup 1.0000x reference)
#include <cuda_runtime.h>
#include <cstdint>

// Problem shape (fixed by the dataset): N=50000 nodes, E=800000 edges, D=256.
#define DIM   256
#define MAXN  50176
#define MAXE  802816

// -------- scratch (static device globals: no runtime allocation) --------
__device__ int   g_deg[MAXN];
__device__ int   g_off[MAXN + 1];
__device__ int   g_cur[MAXN];
__device__ int   g_eidx[MAXE];
__device__ float g_agg[(size_t)MAXN * DIM];

// -------- 1. zero degree counters --------
__global__ void k_zero_deg(int N) {
    int i = blockIdx.x * blockDim.x + threadIdx.x;
    if (i < N) g_deg[i] = 0;
}

// -------- 2. histogram of dst --------
__global__ void k_hist(const int* __restrict__ dst, int E) {
    int e = blockIdx.x * blockDim.x + threadIdx.x;
    if (e < E) atomicAdd(&g_deg[dst[e]], 1);
}

// -------- 3. single-block exclusive scan (shuffle-based) + cursor copy --------
__global__ void k_scan(int N) {
    __shared__ int warp_sums[32];
    __shared__ int s_carry;
    const int tid  = threadIdx.x;           // 1024 threads
    const int lane = tid & 31;
    const int warp = tid >> 5;

    if (tid == 0) s_carry = 0;
    __syncthreads();

    for (int base = 0; base < N; base += 1024) {
        int i = base + tid;
        int v = (i < N) ? g_deg[i] : 0;

        // inclusive warp scan
        int x = v;
        #pragma unroll
        for (int d = 1; d < 32; d <<= 1) {
            int y = __shfl_up_sync(0xffffffffu, x, d);
            if (lane >= d) x += y;
        }
        if (lane == 31) warp_sums[warp] = x;
        __syncthreads();
        if (warp == 0) {
            int ws = warp_sums[lane];
            #pragma unroll
            for (int d = 1; d < 32; d <<= 1) {
                int y = __shfl_up_sync(0xffffffffu, ws, d);
                if (lane >= d) ws += y;
            }
            warp_sums[lane] = ws;
        }
        __syncthreads();

        int warp_off = (warp == 0) ? 0 : warp_sums[warp - 1];
        int incl = x + warp_off + s_carry;   // inclusive over all processed so far
        int excl = incl - v;
        if (i < N) g_off[i] = excl;

        __syncthreads();                      // everyone has read s_carry
        if (tid == 1023) s_carry = incl;      // tail thread: v=0 if OOB -> total
        __syncthreads();
    }
    if (tid == 0) g_off[N] = s_carry;
    __syncthreads();

    // copy offsets -> cursors for the bucket pass
    for (int i = tid; i < N; i += 1024) g_cur[i] = g_off[i];
}

// -------- 4. bucket edge ids by dst --------
__global__ void k_bucket(const int* __restrict__ dst, int E) {
    int e = blockIdx.x * blockDim.x + threadIdx.x;
    if (e < E) {
        int pos = atomicAdd(&g_cur[dst[e]], 1);
        g_eidx[pos] = e;
    }
}

// -------- 5. per-node aggregation: agg[n] = sum_{e in bucket(n)} e_w[e] * h[src[e]] --------
// one block per node, 256 threads = one feature each. No atomics on feature data;
// h (51 MB) is L2-resident, so the gathers are L2-bandwidth work.
#define AGG_CHUNK 64
__global__ void k_agg(const float* __restrict__ h,
                      const float* __restrict__ e_w,
                      const int*   __restrict__ src) {
    const int n = blockIdx.x;
    const int t = threadIdx.x;
    const int beg = g_off[n];
    const int end = g_off[n + 1];

    __shared__ int   s_src[AGG_CHUNK];
    __shared__ float s_w[AGG_CHUNK];

    float acc = 0.0f;
    for (int base = beg; base < end; base += AGG_CHUNK) {
        int cnt = end - base;
        if (cnt > AGG_CHUNK) cnt = AGG_CHUNK;
        if (t < cnt) {
            int eid  = g_eidx[base + t];
            s_src[t] = src[eid];
            s_w[t]   = e_w[eid];
        }
        __syncthreads();
        #pragma unroll 4
        for (int i = 0; i < cnt; i++) {
            acc = fmaf(__ldg(&h[(size_t)s_src[i] * DIM + t]), s_w[i], acc);
        }
        __syncthreads();
    }
    g_agg[(size_t)n * DIM + t] = acc;
}

// -------- 6. GEMM: out[M,256] = agg[M,256] @ W[256,256] + bias --------
// 64x64 tile, BK=16, 256 threads, 4x4 microtile per thread, fp32.
#define BM 64
#define BN 64
#define BK 16
__global__ void k_gemm(const float* __restrict__ B,     // weight [256,256]
                       const float* __restrict__ bias,  // [256]
                       float* __restrict__ C, int M) {
    __shared__ float As[BM][BK];        // [m][k]
    __shared__ float Bs[BK][BN];        // [k][n]

    const int tid = threadIdx.x;        // 256
    const int tx  = tid & 15;           // 0..15 -> n
    const int ty  = tid >> 4;           // 0..15 -> m
    const int tile_m = blockIdx.y * BM;
    const int tile_n = blockIdx.x * BN;
    const float* A = g_agg;

    float c[4][4] = {};

    for (int k0 = 0; k0 < DIM; k0 += BK) {
        // load A tile: 64x16 = 1024 elems, 4 per thread. idx -> (m = idx/16, k = idx%16)
        #pragma unroll
        for (int i = 0; i < 4; i++) {
            int idx = tid + i * 256;
            int m = idx >> 4;
            int k = idx & 15;
            int gm = tile_m + m;
            As[m][k] = (gm < M) ? A[(size_t)gm * DIM + k0 + k] : 0.0f;
        }
        // load B tile: 16x64, idx -> (k = idx/64, n = idx%64), fully coalesced
        #pragma unroll
        for (int i = 0; i < 4; i++) {
            int idx = tid + i * 256;
            int k = idx >> 6;
            int n = idx & 63;
            Bs[k][n] = B[(size_t)(k0 + k) * DIM + tile_n + n];
        }
        __syncthreads();

        #pragma unroll
        for (int k = 0; k < BK; k++) {
            float a0 = As[ty * 4 + 0][k];
            float a1 = As[ty * 4 + 1][k];
            float a2 = As[ty * 4 + 2][k];
            float a3 = As[ty * 4 + 3][k];
            float4 b = *reinterpret_cast<const float4*>(&Bs[k][tx * 4]);
            c[0][0] = fmaf(a0, b.x, c[0][0]); c[0][1] = fmaf(a0, b.y, c[0][1]);
            c[0][2] = fmaf(a0, b.z, c[0][2]); c[0][3] = fmaf(a0, b.w, c[0][3]);
            c[1][0] = fmaf(a1, b.x, c[1][0]); c[1][1] = fmaf(a1, b.y, c[1][1]);
            c[1][2] = fmaf(a1, b.z, c[1][2]); c[1][3] = fmaf(a1, b.w, c[1][3]);
            c[2][0] = fmaf(a2, b.x, c[2][0]); c[2][1] = fmaf(a2, b.y, c[2][1]);
            c[2][2] = fmaf(a2, b.z, c[2][2]); c[2][3] = fmaf(a2, b.w, c[2][3]);
            c[3][0] = fmaf(a3, b.x, c[3][0]); c[3][1] = fmaf(a3, b.y, c[3][1]);
            c[3][2] = fmaf(a3, b.z, c[3][2]); c[3][3] = fmaf(a3, b.w, c[3][3]);
        }
        __syncthreads();
    }

    #pragma unroll
    for (int i = 0; i < 4; i++) {
        int gm = tile_m + ty * 4 + i;
        if (gm >= M) continue;
        int gn = tile_n + tx * 4;
        float4 out;
        out.x = c[i][0] + bias[gn + 0];
        out.y = c[i][1] + bias[gn + 1];
        out.z = c[i][2] + bias[gn + 2];
        out.w = c[i][3] + bias[gn + 3];
        *reinterpret_cast<float4*>(&C[(size_t)gm * DIM + gn]) = out;
    }
}

extern "C" void kernel_launch(void* const* d_in, const int* in_sizes, int n_in,
                              void* d_out, int out_size) {
    const float* h      = (const float*)d_in[0];   // [N, 256]
    const float* e_w    = (const float*)d_in[1];   // [E, 1]
    const int*   src    = (const int*)  d_in[2];   // [E]
    const int*   dst    = (const int*)  d_in[3];   // [E]
    const float* weight = (const float*)d_in[4];   // [256, 256]
    const float* bias   = (const float*)d_in[5];   // [256]
    float* out = (float*)d_out;                    // [N, 256]

    const int N = in_sizes[0] / DIM;
    const int E = in_sizes[2];

    k_zero_deg<<<(N + 255) / 256, 256>>>(N);
    k_hist<<<(E + 255) / 256, 256>>>(dst, E);
    k_scan<<<1, 1024>>>(N);
    k_bucket<<<(E + 255) / 256, 256>>>(dst, E);
    k_agg<<<N, DIM>>>(h, e_w, src);

    dim3 gemm_grid(DIM / BN, (N + BM - 1) / BM);
    k_gemm<<<gemm_grid, 256>>>(weight, bias, out, N);
}

// round 8
// speedup vs baseline: 1.5467x; 1.5467x over previous
#include <cuda_runtime.h>
#include <cstdint>

// Problem shape (fixed by the dataset): N=50000 nodes, E=800000 edges, D=256.
#define DIM   256
#define MAXN  50176
#define MAXE  802816

// -------- scratch (static device globals: no runtime allocation) --------
__device__ int   g_deg[MAXN];
__device__ int   g_off[MAXN + 1];
__device__ int   g_cur[MAXN];
__device__ int   g_esrc[MAXE];    // bucketed src ids
__device__ float g_ew[MAXE];      // bucketed edge weights
__device__ float g_agg[(size_t)MAXN * DIM];   // zero-initialized device global

// -------- 1. zero degree counters --------
__global__ void k_zero_deg(int N) {
    int i = blockIdx.x * blockDim.x + threadIdx.x;
    if (i < N) g_deg[i] = 0;
}

// -------- 2. histogram of dst --------
__global__ void k_hist(const int* __restrict__ dst, int E) {
    int e = blockIdx.x * blockDim.x + threadIdx.x;
    if (e < E) atomicAdd(&g_deg[dst[e]], 1);
}

// -------- 3. single-block exclusive scan (shuffle-based) + cursor copy --------
__global__ void k_scan(int N) {
    __shared__ int warp_sums[32];
    __shared__ int s_carry;
    const int tid  = threadIdx.x;           // 1024 threads
    const int lane = tid & 31;
    const int warp = tid >> 5;

    if (tid == 0) s_carry = 0;
    __syncthreads();

    for (int base = 0; base < N; base += 1024) {
        int i = base + tid;
        int v = (i < N) ? g_deg[i] : 0;

        int x = v;
        #pragma unroll
        for (int d = 1; d < 32; d <<= 1) {
            int y = __shfl_up_sync(0xffffffffu, x, d);
            if (lane >= d) x += y;
        }
        if (lane == 31) warp_sums[warp] = x;
        __syncthreads();
        if (warp == 0) {
            int ws = warp_sums[lane];
            #pragma unroll
            for (int d = 1; d < 32; d <<= 1) {
                int y = __shfl_up_sync(0xffffffffu, ws, d);
                if (lane >= d) ws += y;
            }
            warp_sums[lane] = ws;
        }
        __syncthreads();

        int warp_off = (warp == 0) ? 0 : warp_sums[warp - 1];
        int incl = x + warp_off + s_carry;
        int excl = incl - v;
        if (i < N) g_off[i] = excl;

        __syncthreads();
        if (tid == 1023) s_carry = incl;
        __syncthreads();
    }
    if (tid == 0) g_off[N] = s_carry;
    __syncthreads();

    for (int i = tid; i < N; i += 1024) g_cur[i] = g_off[i];
}

// -------- 4. bucket (src, weight) pairs by dst --------
__global__ void k_bucket(const int* __restrict__ src,
                         const int* __restrict__ dst,
                         const float* __restrict__ e_w, int E) {
    int e = blockIdx.x * blockDim.x + threadIdx.x;
    if (e < E) {
        int pos = atomicAdd(&g_cur[dst[e]], 1);
        g_esrc[pos] = src[e];
        g_ew[pos]   = e_w[e];
    }
}

// -------- 5. per-node aggregation --------
#define AGG_CHUNK 64
__global__ void k_agg(const float* __restrict__ h) {
    const int n = blockIdx.x;
    const int t = threadIdx.x;
    const int beg = g_off[n];
    const int end = g_off[n + 1];

    __shared__ int   s_src[AGG_CHUNK];
    __shared__ float s_w[AGG_CHUNK];

    float acc = 0.0f;
    for (int base = beg; base < end; base += AGG_CHUNK) {
        int cnt = end - base;
        if (cnt > AGG_CHUNK) cnt = AGG_CHUNK;
        if (t < cnt) {
            s_src[t] = g_esrc[base + t];   // coalesced
            s_w[t]   = g_ew[base + t];     // coalesced
        }
        __syncthreads();
        #pragma unroll 4
        for (int i = 0; i < cnt; i++) {
            acc = fmaf(__ldg(&h[(size_t)s_src[i] * DIM + t]), s_w[i], acc);
        }
        __syncthreads();
    }
    g_agg[(size_t)n * DIM + t] = acc;
}

// -------- 6. TF32 tensor-core GEMM: out = agg @ W + bias --------
// 128x64 tile, BK=32, 256 threads (8 warps), warp = 32x32 (2x4 m16n8 tiles).
#define GBM 128
#define GBN 64
#define GBK 32
#define A_PITCH 36      // conflict-free fragment reads: (4m+k)%32 all distinct
#define B_PITCH 72      // conflict-free fragment reads: (8k+n)%32 all distinct

__device__ __forceinline__ float to_tf32(float x) {
    float y;
    asm("cvt.rna.tf32.f32 %0, %1;" : "=f"(y) : "f"(x));
    return y;
}

__device__ __forceinline__ void mma_tf32(float& d0, float& d1, float& d2, float& d3,
                                         uint32_t a0, uint32_t a1, uint32_t a2, uint32_t a3,
                                         uint32_t b0, uint32_t b1) {
    asm volatile(
        "mma.sync.aligned.m16n8k8.row.col.f32.tf32.tf32.f32 "
        "{%0,%1,%2,%3}, {%4,%5,%6,%7}, {%8,%9}, {%0,%1,%2,%3};"
        : "+f"(d0), "+f"(d1), "+f"(d2), "+f"(d3)
        : "r"(a0), "r"(a1), "r"(a2), "r"(a3), "r"(b0), "r"(b1));
}

__global__ __launch_bounds__(256)
void k_gemm_tf32(const float* __restrict__ W,     // [256,256] row-major (k, n)
                 const float* __restrict__ bias,  // [256]
                 float* __restrict__ C, int M) {
    __shared__ float As[GBM * A_PITCH];   // [m][k], pitch 36
    __shared__ float Bs[GBK * B_PITCH];   // [k][n], pitch 72
    __shared__ float sBias[GBN];

    const int tid    = threadIdx.x;
    const int warp   = tid >> 5;
    const int lane   = tid & 31;
    const int gid    = lane >> 2;          // 0..7
    const int tig    = lane & 3;           // 0..3
    const int warp_m = warp >> 1;          // 0..3
    const int warp_n = warp & 1;           // 0..1
    const int wm0    = warp_m * 32;
    const int wn0    = warp_n * 32;
    const int tile_m = blockIdx.y * GBM;
    const int tile_n = blockIdx.x * GBN;
    const float* A   = g_agg;              // rows beyond M are 0 (zero-init global)

    if (tid < GBN) sBias[tid] = bias[tile_n + tid];

    float acc[2][4][4];
    #pragma unroll
    for (int i = 0; i < 2; i++)
        #pragma unroll
        for (int j = 0; j < 4; j++)
            #pragma unroll
            for (int r = 0; r < 4; r++) acc[i][j][r] = 0.0f;

    const int a_row = tid >> 3;            // 0..31 (32 rows per pass, 4 passes)
    const int a_q   = tid & 7;             // float4 column index
    const int b_row = tid >> 4;            // 0..15 (16 rows per pass, 2 passes)
    const int b_q   = tid & 15;            // float4 column index

    for (int k0 = 0; k0 < DIM; k0 += GBK) {
        // ---- stage A tile (128x32) ----
        #pragma unroll
        for (int it = 0; it < 4; it++) {
            int m  = a_row + it * 32;
            float4 v = *reinterpret_cast<const float4*>(
                &A[(size_t)(tile_m + m) * DIM + k0 + a_q * 4]);
            v.x = to_tf32(v.x); v.y = to_tf32(v.y);
            v.z = to_tf32(v.z); v.w = to_tf32(v.w);
            *reinterpret_cast<float4*>(&As[m * A_PITCH + a_q * 4]) = v;
        }
        // ---- stage B tile (32x64) ----
        #pragma unroll
        for (int it = 0; it < 2; it++) {
            int k = b_row + it * 16;
            float4 v = *reinterpret_cast<const float4*>(
                &W[(size_t)(k0 + k) * DIM + tile_n + b_q * 4]);
            v.x = to_tf32(v.x); v.y = to_tf32(v.y);
            v.z = to_tf32(v.z); v.w = to_tf32(v.w);
            *reinterpret_cast<float4*>(&Bs[k * B_PITCH + b_q * 4]) = v;
        }
        __syncthreads();

        #pragma unroll
        for (int kk = 0; kk < GBK / 8; kk++) {
            const int kb = kk * 8;
            uint32_t a[2][4], b[4][2];
            #pragma unroll
            for (int mt = 0; mt < 2; mt++) {
                int m0 = wm0 + mt * 16;
                a[mt][0] = __float_as_uint(As[(m0 + gid)     * A_PITCH + kb + tig]);
                a[mt][1] = __float_as_uint(As[(m0 + 8 + gid) * A_PITCH + kb + tig]);
                a[mt][2] = __float_as_uint(As[(m0 + gid)     * A_PITCH + kb + tig + 4]);
                a[mt][3] = __float_as_uint(As[(m0 + 8 + gid) * A_PITCH + kb + tig + 4]);
            }
            #pragma unroll
            for (int nt = 0; nt < 4; nt++) {
                int n0 = wn0 + nt * 8 + gid;
                b[nt][0] = __float_as_uint(Bs[(kb + tig)     * B_PITCH + n0]);
                b[nt][1] = __float_as_uint(Bs[(kb + tig + 4) * B_PITCH + n0]);
            }
            #pragma unroll
            for (int mt = 0; mt < 2; mt++)
                #pragma unroll
                for (int nt = 0; nt < 4; nt++)
                    mma_tf32(acc[mt][nt][0], acc[mt][nt][1], acc[mt][nt][2], acc[mt][nt][3],
                             a[mt][0], a[mt][1], a[mt][2], a[mt][3],
                             b[nt][0], b[nt][1]);
        }
        __syncthreads();
    }

    // ---- epilogue: add bias, store fp32 ----
    #pragma unroll
    for (int mt = 0; mt < 2; mt++) {
        int r0 = tile_m + wm0 + mt * 16 + gid;
        int r1 = r0 + 8;
        #pragma unroll
        for (int nt = 0; nt < 4; nt++) {
            int cl = wn0 + nt * 8 + tig * 2;   // local col within tile
            int gc = tile_n + cl;
            float b0 = sBias[cl], b1 = sBias[cl + 1];
            if (r0 < M) {
                float2 o; o.x = acc[mt][nt][0] + b0; o.y = acc[mt][nt][1] + b1;
                *reinterpret_cast<float2*>(&C[(size_t)r0 * DIM + gc]) = o;
            }
            if (r1 < M) {
                float2 o; o.x = acc[mt][nt][2] + b0; o.y = acc[mt][nt][3] + b1;
                *reinterpret_cast<float2*>(&C[(size_t)r1 * DIM + gc]) = o;
            }
        }
    }
}

extern "C" void kernel_launch(void* const* d_in, const int* in_sizes, int n_in,
                              void* d_out, int out_size) {
    const float* h      = (const float*)d_in[0];   // [N, 256]
    const float* e_w    = (const float*)d_in[1];   // [E, 1]
    const int*   src    = (const int*)  d_in[2];   // [E]
    const int*   dst    = (const int*)  d_in[3];   // [E]
    const float* weight = (const float*)d_in[4];   // [256, 256]
    const float* bias   = (const float*)d_in[5];   // [256]
    float* out = (float*)d_out;                    // [N, 256]

    const int N = in_sizes[0] / DIM;
    const int E = in_sizes[2];

    k_zero_deg<<<(N + 255) / 256, 256>>>(N);
    k_hist<<<(E + 255) / 256, 256>>>(dst, E);
    k_scan<<<1, 1024>>>(N);
    k_bucket<<<(E + 255) / 256, 256>>>(src, dst, e_w, E);
    k_agg<<<N, DIM>>>(h);

    dim3 gemm_grid(DIM / GBN, (N + GBM - 1) / GBM);
    k_gemm_tf32<<<gemm_grid, 256>>>(weight, bias, out, N);
}

// round 11
// speedup vs baseline: 2.1616x; 1.3976x over previous
#include <cuda_runtime.h>
#include <cstdint>

// Problem shape (fixed by the dataset): N=50000 nodes, E=800000 edges, D=256.
#define DIM   256
#define MAXN  50176
#define MAXE  802816

// -------- scratch (static device globals: no runtime allocation) --------
__device__ int   g_deg[MAXN];
__device__ int   g_off[MAXN + 1];
__device__ int   g_cur[MAXN];
__device__ int   g_esrc[MAXE];    // bucketed src ids
__device__ float g_ew[MAXE];      // bucketed edge weights
__device__ __align__(16) float g_agg[(size_t)MAXN * DIM];   // rows >= N stay zero (GEMM padding)

// -------- 1. zero degree counters --------
__global__ void k_zero_deg(int N) {
    int i = blockIdx.x * blockDim.x + threadIdx.x;
    if (i < N) g_deg[i] = 0;
}

// -------- 2. histogram of dst (int4-vectorized) --------
__global__ void k_hist(const int4* __restrict__ dst4, int E4) {
    int e = blockIdx.x * blockDim.x + threadIdx.x;
    if (e < E4) {
        int4 d = dst4[e];
        atomicAdd(&g_deg[d.x], 1);
        atomicAdd(&g_deg[d.y], 1);
        atomicAdd(&g_deg[d.z], 1);
        atomicAdd(&g_deg[d.w], 1);
    }
}
__global__ void k_hist_tail(const int* __restrict__ dst, int start, int E) {
    int e = start + blockIdx.x * blockDim.x + threadIdx.x;
    if (e < E) atomicAdd(&g_deg[dst[e]], 1);
}

// -------- 3. single-block exclusive scan: 4096 elems / iteration --------
__global__ void k_scan(int N) {
    __shared__ int warp_sums[32];
    __shared__ int s_carry;
    const int tid  = threadIdx.x;           // 1024 threads
    const int lane = tid & 31;
    const int warp = tid >> 5;

    if (tid == 0) s_carry = 0;
    __syncthreads();

    for (int base = 0; base < N; base += 4096) {
        const int i0 = base + tid * 4;
        int v[4];
        #pragma unroll
        for (int j = 0; j < 4; j++) {
            int i = i0 + j;
            v[j] = (i < N) ? g_deg[i] : 0;
        }
        int tsum = v[0] + v[1] + v[2] + v[3];

        // inclusive warp scan of per-thread sums
        int x = tsum;
        #pragma unroll
        for (int d = 1; d < 32; d <<= 1) {
            int y = __shfl_up_sync(0xffffffffu, x, d);
            if (lane >= d) x += y;
        }
        if (lane == 31) warp_sums[warp] = x;
        __syncthreads();
        if (warp == 0) {
            int ws = warp_sums[lane];
            #pragma unroll
            for (int d = 1; d < 32; d <<= 1) {
                int y = __shfl_up_sync(0xffffffffu, ws, d);
                if (lane >= d) ws += y;
            }
            warp_sums[lane] = ws;
        }
        __syncthreads();

        int warp_off = (warp == 0) ? 0 : warp_sums[warp - 1];
        int excl = s_carry + warp_off + (x - tsum);
        #pragma unroll
        for (int j = 0; j < 4; j++) {
            int i = i0 + j;
            if (i < N) g_off[i] = excl;
            excl += v[j];
        }
        __syncthreads();                        // everyone has read s_carry / warp_sums
        if (tid == 0) s_carry += warp_sums[31]; // add this chunk's total
        __syncthreads();
    }
    if (tid == 0) g_off[N] = s_carry;
    __syncthreads();

    for (int i = tid; i < N; i += 1024) g_cur[i] = g_off[i];
}

// -------- 4. bucket (src, weight) pairs by dst --------
__global__ void k_bucket(const int* __restrict__ src,
                         const int* __restrict__ dst,
                         const float* __restrict__ e_w, int E) {
    int e = blockIdx.x * blockDim.x + threadIdx.x;
    if (e < E) {
        int pos = atomicAdd(&g_cur[dst[e]], 1);
        g_esrc[pos] = src[e];
        g_ew[pos]   = e_w[e];
    }
}

// -------- 5. per-node aggregation: 4 nodes/block, float4 lanes, no smem/sync --------
__global__ __launch_bounds__(256)
void k_agg(const float4* __restrict__ h4, int N) {
    const int t    = threadIdx.x;
    const int grp  = t >> 6;            // 0..3: node within block
    const int lane = t & 63;            // float4 feature index
    const int n = blockIdx.x * 4 + grp;
    if (n >= N) return;

    int i        = g_off[n];
    const int end = g_off[n + 1];

    float4 acc = make_float4(0.f, 0.f, 0.f, 0.f);

    // unroll-4: 4 independent 16B gathers in flight per thread
    for (; i + 4 <= end; i += 4) {
        int   s0 = g_esrc[i],   s1 = g_esrc[i+1], s2 = g_esrc[i+2], s3 = g_esrc[i+3];
        float w0 = g_ew[i],     w1 = g_ew[i+1],   w2 = g_ew[i+2],   w3 = g_ew[i+3];
        float4 v0 = __ldg(&h4[(size_t)s0 * 64 + lane]);
        float4 v1 = __ldg(&h4[(size_t)s1 * 64 + lane]);
        float4 v2 = __ldg(&h4[(size_t)s2 * 64 + lane]);
        float4 v3 = __ldg(&h4[(size_t)s3 * 64 + lane]);
        acc.x = fmaf(v0.x, w0, acc.x); acc.y = fmaf(v0.y, w0, acc.y);
        acc.z = fmaf(v0.z, w0, acc.z); acc.w = fmaf(v0.w, w0, acc.w);
        acc.x = fmaf(v1.x, w1, acc.x); acc.y = fmaf(v1.y, w1, acc.y);
        acc.z = fmaf(v1.z, w1, acc.z); acc.w = fmaf(v1.w, w1, acc.w);
        acc.x = fmaf(v2.x, w2, acc.x); acc.y = fmaf(v2.y, w2, acc.y);
        acc.z = fmaf(v2.z, w2, acc.z); acc.w = fmaf(v2.w, w2, acc.w);
        acc.x = fmaf(v3.x, w3, acc.x); acc.y = fmaf(v3.y, w3, acc.y);
        acc.z = fmaf(v3.z, w3, acc.z); acc.w = fmaf(v3.w, w3, acc.w);
    }
    for (; i < end; i++) {
        int   s = g_esrc[i];
        float w = g_ew[i];
        float4 v = __ldg(&h4[(size_t)s * 64 + lane]);
        acc.x = fmaf(v.x, w, acc.x); acc.y = fmaf(v.y, w, acc.y);
        acc.z = fmaf(v.z, w, acc.z); acc.w = fmaf(v.w, w, acc.w);
    }

    reinterpret_cast<float4*>(g_agg)[(size_t)n * 64 + lane] = acc;
}

// -------- 6. TF32 tensor-core GEMM with register-prefetch pipelining --------
// 128x64 tile, BK=32, 256 threads (8 warps), warp = 32x32 (2x4 m16n8 tiles).
#define GBM 128
#define GBN 64
#define GBK 32
#define A_PITCH 36
#define B_PITCH 72

__device__ __forceinline__ float to_tf32(float x) {
    float y;
    asm("cvt.rna.tf32.f32 %0, %1;" : "=f"(y) : "f"(x));
    return y;
}

__device__ __forceinline__ void mma_tf32(float& d0, float& d1, float& d2, float& d3,
                                         uint32_t a0, uint32_t a1, uint32_t a2, uint32_t a3,
                                         uint32_t b0, uint32_t b1) {
    asm volatile(
        "mma.sync.aligned.m16n8k8.row.col.f32.tf32.tf32.f32 "
        "{%0,%1,%2,%3}, {%4,%5,%6,%7}, {%8,%9}, {%0,%1,%2,%3};"
        : "+f"(d0), "+f"(d1), "+f"(d2), "+f"(d3)
        : "r"(a0), "r"(a1), "r"(a2), "r"(a3), "r"(b0), "r"(b1));
}

__global__ __launch_bounds__(256)
void k_gemm_tf32(const float* __restrict__ W,     // [256,256] row-major (k, n)
                 const float* __restrict__ bias,  // [256]
                 float* __restrict__ C, int M) {
    __shared__ float As[GBM * A_PITCH];   // [m][k], pitch 36
    __shared__ float Bs[GBK * B_PITCH];   // [k][n], pitch 72
    __shared__ float sBias[GBN];

    const int tid    = threadIdx.x;
    const int warp   = tid >> 5;
    const int lane   = tid & 31;
    const int gid    = lane >> 2;          // 0..7
    const int tig    = lane & 3;           // 0..3
    const int warp_m = warp >> 1;          // 0..3
    const int warp_n = warp & 1;           // 0..1
    const int wm0    = warp_m * 32;
    const int wn0    = warp_n * 32;
    const int tile_m = blockIdx.y * GBM;
    const int tile_n = blockIdx.x * GBN;
    const float* A   = g_agg;              // rows beyond M are 0 (zero-init global)

    if (tid < GBN) sBias[tid] = bias[tile_n + tid];

    float acc[2][4][4];
    #pragma unroll
    for (int i = 0; i < 2; i++)
        #pragma unroll
        for (int j = 0; j < 4; j++)
            #pragma unroll
            for (int r = 0; r < 4; r++) acc[i][j][r] = 0.0f;

    const int a_row = tid >> 3;            // 0..31 (32 rows per pass, 4 passes)
    const int a_q   = tid & 7;             // float4 column index
    const int b_row = tid >> 4;            // 0..15 (16 rows per pass, 2 passes)
    const int b_q   = tid & 15;            // float4 column index

    float4 ra[4], rb[2];

    // prefetch chunk 0
    #pragma unroll
    for (int it = 0; it < 4; it++)
        ra[it] = *reinterpret_cast<const float4*>(
            &A[(size_t)(tile_m + a_row + it * 32) * DIM + a_q * 4]);
    #pragma unroll
    for (int it = 0; it < 2; it++)
        rb[it] = *reinterpret_cast<const float4*>(
            &W[(size_t)(b_row + it * 16) * DIM + tile_n + b_q * 4]);

    const int NK = DIM / GBK;   // 8
    for (int kt = 0; kt < NK; kt++) {
        // ---- store prefetched chunk to smem (with tf32 rounding) ----
        #pragma unroll
        for (int it = 0; it < 4; it++) {
            float4 v = ra[it];
            v.x = to_tf32(v.x); v.y = to_tf32(v.y);
            v.z = to_tf32(v.z); v.w = to_tf32(v.w);
            *reinterpret_cast<float4*>(&As[(a_row + it * 32) * A_PITCH + a_q * 4]) = v;
        }
        #pragma unroll
        for (int it = 0; it < 2; it++) {
            float4 v = rb[it];
            v.x = to_tf32(v.x); v.y = to_tf32(v.y);
            v.z = to_tf32(v.z); v.w = to_tf32(v.w);
            *reinterpret_cast<float4*>(&Bs[(b_row + it * 16) * B_PITCH + b_q * 4]) = v;
        }
        __syncthreads();

        // ---- issue next chunk's global loads (overlap with MMA burst) ----
        if (kt + 1 < NK) {
            const int k0 = (kt + 1) * GBK;
            #pragma unroll
            for (int it = 0; it < 4; it++)
                ra[it] = *reinterpret_cast<const float4*>(
                    &A[(size_t)(tile_m + a_row + it * 32) * DIM + k0 + a_q * 4]);
            #pragma unroll
            for (int it = 0; it < 2; it++)
                rb[it] = *reinterpret_cast<const float4*>(
                    &W[(size_t)(k0 + b_row + it * 16) * DIM + tile_n + b_q * 4]);
        }

        // ---- compute on current chunk ----
        #pragma unroll
        for (int kk = 0; kk < GBK / 8; kk++) {
            const int kb = kk * 8;
            uint32_t a[2][4], b[4][2];
            #pragma unroll
            for (int mt = 0; mt < 2; mt++) {
                int m0 = wm0 + mt * 16;
                a[mt][0] = __float_as_uint(As[(m0 + gid)     * A_PITCH + kb + tig]);
                a[mt][1] = __float_as_uint(As[(m0 + 8 + gid) * A_PITCH + kb + tig]);
                a[mt][2] = __float_as_uint(As[(m0 + gid)     * A_PITCH + kb + tig + 4]);
                a[mt][3] = __float_as_uint(As[(m0 + 8 + gid) * A_PITCH + kb + tig + 4]);
            }
            #pragma unroll
            for (int nt = 0; nt < 4; nt++) {
                int n0 = wn0 + nt * 8 + gid;
                b[nt][0] = __float_as_uint(Bs[(kb + tig)     * B_PITCH + n0]);
                b[nt][1] = __float_as_uint(Bs[(kb + tig + 4) * B_PITCH + n0]);
            }
            #pragma unroll
            for (int mt = 0; mt < 2; mt++)
                #pragma unroll
                for (int nt = 0; nt < 4; nt++)
                    mma_tf32(acc[mt][nt][0], acc[mt][nt][1], acc[mt][nt][2], acc[mt][nt][3],
                             a[mt][0], a[mt][1], a[mt][2], a[mt][3],
                             b[nt][0], b[nt][1]);
        }
        __syncthreads();
    }

    // ---- epilogue: add bias, store fp32 ----
    #pragma unroll
    for (int mt = 0; mt < 2; mt++) {
        int r0 = tile_m + wm0 + mt * 16 + gid;
        int r1 = r0 + 8;
        #pragma unroll
        for (int nt = 0; nt < 4; nt++) {
            int cl = wn0 + nt * 8 + tig * 2;
            int gc = tile_n + cl;
            float b0 = sBias[cl], b1 = sBias[cl + 1];
            if (r0 < M) {
                float2 o; o.x = acc[mt][nt][0] + b0; o.y = acc[mt][nt][1] + b1;
                *reinterpret_cast<float2*>(&C[(size_t)r0 * DIM + gc]) = o;
            }
            if (r1 < M) {
                float2 o; o.x = acc[mt][nt][2] + b0; o.y = acc[mt][nt][3] + b1;
                *reinterpret_cast<float2*>(&C[(size_t)r1 * DIM + gc]) = o;
            }
        }
    }
}

extern "C" void kernel_launch(void* const* d_in, const int* in_sizes, int n_in,
                              void* d_out, int out_size) {
    const float* h      = (const float*)d_in[0];   // [N, 256]
    const float* e_w    = (const float*)d_in[1];   // [E, 1]
    const int*   src    = (const int*)  d_in[2];   // [E]
    const int*   dst    = (const int*)  d_in[3];   // [E]
    const float* weight = (const float*)d_in[4];   // [256, 256]
    const float* bias   = (const float*)d_in[5];   // [256]
    float* out = (float*)d_out;                    // [N, 256]

    const int N = in_sizes[0] / DIM;
    const int E = in_sizes[2];

    k_zero_deg<<<(N + 255) / 256, 256>>>(N);

    const int E4 = E / 4;
    if (E4 > 0)
        k_hist<<<(E4 + 255) / 256, 256>>>((const int4*)dst, E4);
    if (E4 * 4 < E)
        k_hist_tail<<<1, 256>>>(dst, E4 * 4, E);

    k_scan<<<1, 1024>>>(N);
    k_bucket<<<(E + 255) / 256, 256>>>(src, dst, e_w, E);
    k_agg<<<(N + 3) / 4, 256>>>((const float4*)h, N);

    dim3 gemm_grid(DIM / GBN, (N + GBM - 1) / GBM);
    k_gemm_tf32<<<gemm_grid, 256>>>(weight, bias, out, N);
}

// round 12
// speedup vs baseline: 2.1869x; 1.0117x over previous
#include <cuda_runtime.h>
#include <cuda_fp16.h>
#include <cstdint>

// Problem shape (fixed by the dataset): N=50000 nodes, E=800000 edges, D=256.
#define DIM   256
#define MAXN  50176
#define MAXE  802816

// -------- scratch (static device globals: no runtime allocation) --------
__device__ int   g_deg[MAXN];
__device__ int   g_off[MAXN + 1];
__device__ int   g_cur[MAXN];
__device__ __align__(16) int2   g_edge[MAXE];                 // bucketed (src, w_bits)
__device__ __align__(16) __half g_h16[(size_t)MAXN * DIM];    // fp16 copy of h
__device__ __align__(16) float  g_agg[(size_t)MAXN * DIM];    // rows >= N stay zero (GEMM padding)

// -------- 0. convert h to fp16 (one streaming pass) --------
__global__ void k_h2half(const float4* __restrict__ h4, int total4) {
    int i = blockIdx.x * blockDim.x + threadIdx.x;
    if (i < total4) {
        float4 v = h4[i];
        uint2 u;
        *reinterpret_cast<__half2*>(&u.x) = __floats2half2_rn(v.x, v.y);
        *reinterpret_cast<__half2*>(&u.y) = __floats2half2_rn(v.z, v.w);
        reinterpret_cast<uint2*>(g_h16)[i] = u;
    }
}

// -------- 1. zero degree counters --------
__global__ void k_zero_deg(int N) {
    int i = blockIdx.x * blockDim.x + threadIdx.x;
    if (i < N) g_deg[i] = 0;
}

// -------- 2. histogram of dst (int4-vectorized) --------
__global__ void k_hist(const int4* __restrict__ dst4, int E4) {
    int e = blockIdx.x * blockDim.x + threadIdx.x;
    if (e < E4) {
        int4 d = dst4[e];
        atomicAdd(&g_deg[d.x], 1);
        atomicAdd(&g_deg[d.y], 1);
        atomicAdd(&g_deg[d.z], 1);
        atomicAdd(&g_deg[d.w], 1);
    }
}
__global__ void k_hist_tail(const int* __restrict__ dst, int start, int E) {
    int e = start + blockIdx.x * blockDim.x + threadIdx.x;
    if (e < E) atomicAdd(&g_deg[dst[e]], 1);
}

// -------- 3. single-block exclusive scan: 4096 elems / iteration --------
__global__ void k_scan(int N) {
    __shared__ int warp_sums[32];
    __shared__ int s_carry;
    const int tid  = threadIdx.x;           // 1024 threads
    const int lane = tid & 31;
    const int warp = tid >> 5;

    if (tid == 0) s_carry = 0;
    __syncthreads();

    for (int base = 0; base < N; base += 4096) {
        const int i0 = base + tid * 4;
        int v[4];
        #pragma unroll
        for (int j = 0; j < 4; j++) {
            int i = i0 + j;
            v[j] = (i < N) ? g_deg[i] : 0;
        }
        int tsum = v[0] + v[1] + v[2] + v[3];

        int x = tsum;
        #pragma unroll
        for (int d = 1; d < 32; d <<= 1) {
            int y = __shfl_up_sync(0xffffffffu, x, d);
            if (lane >= d) x += y;
        }
        if (lane == 31) warp_sums[warp] = x;
        __syncthreads();
        if (warp == 0) {
            int ws = warp_sums[lane];
            #pragma unroll
            for (int d = 1; d < 32; d <<= 1) {
                int y = __shfl_up_sync(0xffffffffu, ws, d);
                if (lane >= d) ws += y;
            }
            warp_sums[lane] = ws;
        }
        __syncthreads();

        int warp_off = (warp == 0) ? 0 : warp_sums[warp - 1];
        int excl = s_carry + warp_off + (x - tsum);
        #pragma unroll
        for (int j = 0; j < 4; j++) {
            int i = i0 + j;
            if (i < N) g_off[i] = excl;
            excl += v[j];
        }
        __syncthreads();
        if (tid == 0) s_carry += warp_sums[31];
        __syncthreads();
    }
    if (tid == 0) g_off[N] = s_carry;
    __syncthreads();

    for (int i = tid; i < N; i += 1024) g_cur[i] = g_off[i];
}

// -------- 4. bucket packed (src, w_bits) by dst: ONE 8B scattered store/edge --------
__global__ void k_bucket(const int* __restrict__ src,
                         const int* __restrict__ dst,
                         const float* __restrict__ e_w, int E) {
    int e = blockIdx.x * blockDim.x + threadIdx.x;
    if (e < E) {
        int pos = atomicAdd(&g_cur[dst[e]], 1);
        g_edge[pos] = make_int2(src[e], __float_as_int(e_w[e]));
    }
}

// -------- 5. per-node aggregation on fp16 h: 4 nodes/block, 8B lanes, fp32 accum --------
__global__ __launch_bounds__(256)
void k_agg(int N) {
    const int t    = threadIdx.x;
    const int grp  = t >> 6;            // 0..3: node within block
    const int lane = t & 63;            // uint2 (4-feature) index within row
    const int n = blockIdx.x * 4 + grp;
    if (n >= N) return;

    const uint2* __restrict__ h16 = reinterpret_cast<const uint2*>(g_h16);

    int i         = g_off[n];
    const int end = g_off[n + 1];

    float4 acc = make_float4(0.f, 0.f, 0.f, 0.f);

    // unroll-4: 4 independent 8B gathers in flight per thread
    for (; i + 4 <= end; i += 4) {
        int2 e0 = g_edge[i], e1 = g_edge[i+1], e2 = g_edge[i+2], e3 = g_edge[i+3];
        float w0 = __int_as_float(e0.y), w1 = __int_as_float(e1.y);
        float w2 = __int_as_float(e2.y), w3 = __int_as_float(e3.y);
        uint2 u0 = __ldg(&h16[(size_t)e0.x * 64 + lane]);
        uint2 u1 = __ldg(&h16[(size_t)e1.x * 64 + lane]);
        uint2 u2 = __ldg(&h16[(size_t)e2.x * 64 + lane]);
        uint2 u3 = __ldg(&h16[(size_t)e3.x * 64 + lane]);
        {
            float2 a = __half22float2(*reinterpret_cast<const __half2*>(&u0.x));
            float2 b = __half22float2(*reinterpret_cast<const __half2*>(&u0.y));
            acc.x = fmaf(a.x, w0, acc.x); acc.y = fmaf(a.y, w0, acc.y);
            acc.z = fmaf(b.x, w0, acc.z); acc.w = fmaf(b.y, w0, acc.w);
        }
        {
            float2 a = __half22float2(*reinterpret_cast<const __half2*>(&u1.x));
            float2 b = __half22float2(*reinterpret_cast<const __half2*>(&u1.y));
            acc.x = fmaf(a.x, w1, acc.x); acc.y = fmaf(a.y, w1, acc.y);
            acc.z = fmaf(b.x, w1, acc.z); acc.w = fmaf(b.y, w1, acc.w);
        }
        {
            float2 a = __half22float2(*reinterpret_cast<const __half2*>(&u2.x));
            float2 b = __half22float2(*reinterpret_cast<const __half2*>(&u2.y));
            acc.x = fmaf(a.x, w2, acc.x); acc.y = fmaf(a.y, w2, acc.y);
            acc.z = fmaf(b.x, w2, acc.z); acc.w = fmaf(b.y, w2, acc.w);
        }
        {
            float2 a = __half22float2(*reinterpret_cast<const __half2*>(&u3.x));
            float2 b = __half22float2(*reinterpret_cast<const __half2*>(&u3.y));
            acc.x = fmaf(a.x, w3, acc.x); acc.y = fmaf(a.y, w3, acc.y);
            acc.z = fmaf(b.x, w3, acc.z); acc.w = fmaf(b.y, w3, acc.w);
        }
    }
    for (; i < end; i++) {
        int2 e = g_edge[i];
        float w = __int_as_float(e.y);
        uint2 u = __ldg(&h16[(size_t)e.x * 64 + lane]);
        float2 a = __half22float2(*reinterpret_cast<const __half2*>(&u.x));
        float2 b = __half22float2(*reinterpret_cast<const __half2*>(&u.y));
        acc.x = fmaf(a.x, w, acc.x); acc.y = fmaf(a.y, w, acc.y);
        acc.z = fmaf(b.x, w, acc.z); acc.w = fmaf(b.y, w, acc.w);
    }

    reinterpret_cast<float4*>(g_agg)[(size_t)n * 64 + lane] = acc;
}

// -------- 6. TF32 tensor-core GEMM with register-prefetch pipelining --------
// 128x64 tile, BK=32, 256 threads (8 warps), warp = 32x32 (2x4 m16n8 tiles).
#define GBM 128
#define GBN 64
#define GBK 32
#define A_PITCH 36
#define B_PITCH 72

__device__ __forceinline__ float to_tf32(float x) {
    float y;
    asm("cvt.rna.tf32.f32 %0, %1;" : "=f"(y) : "f"(x));
    return y;
}

__device__ __forceinline__ void mma_tf32(float& d0, float& d1, float& d2, float& d3,
                                         uint32_t a0, uint32_t a1, uint32_t a2, uint32_t a3,
                                         uint32_t b0, uint32_t b1) {
    asm volatile(
        "mma.sync.aligned.m16n8k8.row.col.f32.tf32.tf32.f32 "
        "{%0,%1,%2,%3}, {%4,%5,%6,%7}, {%8,%9}, {%0,%1,%2,%3};"
        : "+f"(d0), "+f"(d1), "+f"(d2), "+f"(d3)
        : "r"(a0), "r"(a1), "r"(a2), "r"(a3), "r"(b0), "r"(b1));
}

__global__ __launch_bounds__(256)
void k_gemm_tf32(const float* __restrict__ W,     // [256,256] row-major (k, n)
                 const float* __restrict__ bias,  // [256]
                 float* __restrict__ C, int M) {
    __shared__ float As[GBM * A_PITCH];   // [m][k], pitch 36
    __shared__ float Bs[GBK * B_PITCH];   // [k][n], pitch 72
    __shared__ float sBias[GBN];

    const int tid    = threadIdx.x;
    const int warp   = tid >> 5;
    const int lane   = tid & 31;
    const int gid    = lane >> 2;          // 0..7
    const int tig    = lane & 3;           // 0..3
    const int warp_m = warp >> 1;          // 0..3
    const int warp_n = warp & 1;           // 0..1
    const int wm0    = warp_m * 32;
    const int wn0    = warp_n * 32;
    const int tile_m = blockIdx.y * GBM;
    const int tile_n = blockIdx.x * GBN;
    const float* A   = g_agg;              // rows beyond M are 0 (zero-init global)

    if (tid < GBN) sBias[tid] = bias[tile_n + tid];

    float acc[2][4][4];
    #pragma unroll
    for (int i = 0; i < 2; i++)
        #pragma unroll
        for (int j = 0; j < 4; j++)
            #pragma unroll
            for (int r = 0; r < 4; r++) acc[i][j][r] = 0.0f;

    const int a_row = tid >> 3;            // 0..31 (32 rows per pass, 4 passes)
    const int a_q   = tid & 7;             // float4 column index
    const int b_row = tid >> 4;            // 0..15 (16 rows per pass, 2 passes)
    const int b_q   = tid & 15;            // float4 column index

    float4 ra[4], rb[2];

    // prefetch chunk 0
    #pragma unroll
    for (int it = 0; it < 4; it++)
        ra[it] = *reinterpret_cast<const float4*>(
            &A[(size_t)(tile_m + a_row + it * 32) * DIM + a_q * 4]);
    #pragma unroll
    for (int it = 0; it < 2; it++)
        rb[it] = *reinterpret_cast<const float4*>(
            &W[(size_t)(b_row + it * 16) * DIM + tile_n + b_q * 4]);

    const int NK = DIM / GBK;   // 8
    for (int kt = 0; kt < NK; kt++) {
        // ---- store prefetched chunk to smem (with tf32 rounding) ----
        #pragma unroll
        for (int it = 0; it < 4; it++) {
            float4 v = ra[it];
            v.x = to_tf32(v.x); v.y = to_tf32(v.y);
            v.z = to_tf32(v.z); v.w = to_tf32(v.w);
            *reinterpret_cast<float4*>(&As[(a_row + it * 32) * A_PITCH + a_q * 4]) = v;
        }
        #pragma unroll
        for (int it = 0; it < 2; it++) {
            float4 v = rb[it];
            v.x = to_tf32(v.x); v.y = to_tf32(v.y);
            v.z = to_tf32(v.z); v.w = to_tf32(v.w);
            *reinterpret_cast<float4*>(&Bs[(b_row + it * 16) * B_PITCH + b_q * 4]) = v;
        }
        __syncthreads();

        // ---- issue next chunk's global loads (overlap with MMA burst) ----
        if (kt + 1 < NK) {
            const int k0 = (kt + 1) * GBK;
            #pragma unroll
            for (int it = 0; it < 4; it++)
                ra[it] = *reinterpret_cast<const float4*>(
                    &A[(size_t)(tile_m + a_row + it * 32) * DIM + k0 + a_q * 4]);
            #pragma unroll
            for (int it = 0; it < 2; it++)
                rb[it] = *reinterpret_cast<const float4*>(
                    &W[(size_t)(k0 + b_row + it * 16) * DIM + tile_n + b_q * 4]);
        }

        // ---- compute on current chunk ----
        #pragma unroll
        for (int kk = 0; kk < GBK / 8; kk++) {
            const int kb = kk * 8;
            uint32_t a[2][4], b[4][2];
            #pragma unroll
            for (int mt = 0; mt < 2; mt++) {
                int m0 = wm0 + mt * 16;
                a[mt][0] = __float_as_uint(As[(m0 + gid)     * A_PITCH + kb + tig]);
                a[mt][1] = __float_as_uint(As[(m0 + 8 + gid) * A_PITCH + kb + tig]);
                a[mt][2] = __float_as_uint(As[(m0 + gid)     * A_PITCH + kb + tig + 4]);
                a[mt][3] = __float_as_uint(As[(m0 + 8 + gid) * A_PITCH + kb + tig + 4]);
            }
            #pragma unroll
            for (int nt = 0; nt < 4; nt++) {
                int n0 = wn0 + nt * 8 + gid;
                b[nt][0] = __float_as_uint(Bs[(kb + tig)     * B_PITCH + n0]);
                b[nt][1] = __float_as_uint(Bs[(kb + tig + 4) * B_PITCH + n0]);
            }
            #pragma unroll
            for (int mt = 0; mt < 2; mt++)
                #pragma unroll
                for (int nt = 0; nt < 4; nt++)
                    mma_tf32(acc[mt][nt][0], acc[mt][nt][1], acc[mt][nt][2], acc[mt][nt][3],
                             a[mt][0], a[mt][1], a[mt][2], a[mt][3],
                             b[nt][0], b[nt][1]);
        }
        __syncthreads();
    }

    // ---- epilogue: add bias, store fp32 ----
    #pragma unroll
    for (int mt = 0; mt < 2; mt++) {
        int r0 = tile_m + wm0 + mt * 16 + gid;
        int r1 = r0 + 8;
        #pragma unroll
        for (int nt = 0; nt < 4; nt++) {
            int cl = wn0 + nt * 8 + tig * 2;
            int gc = tile_n + cl;
            float b0 = sBias[cl], b1 = sBias[cl + 1];
            if (r0 < M) {
                float2 o; o.x = acc[mt][nt][0] + b0; o.y = acc[mt][nt][1] + b1;
                *reinterpret_cast<float2*>(&C[(size_t)r0 * DIM + gc]) = o;
            }
            if (r1 < M) {
                float2 o; o.x = acc[mt][nt][2] + b0; o.y = acc[mt][nt][3] + b1;
                *reinterpret_cast<float2*>(&C[(size_t)r1 * DIM + gc]) = o;
            }
        }
    }
}

extern "C" void kernel_launch(void* const* d_in, const int* in_sizes, int n_in,
                              void* d_out, int out_size) {
    const float* h      = (const float*)d_in[0];   // [N, 256]
    const float* e_w    = (const float*)d_in[1];   // [E, 1]
    const int*   src    = (const int*)  d_in[2];   // [E]
    const int*   dst    = (const int*)  d_in[3];   // [E]
    const float* weight = (const float*)d_in[4];   // [256, 256]
    const float* bias   = (const float*)d_in[5];   // [256]
    float* out = (float*)d_out;                    // [N, 256]

    const int N = in_sizes[0] / DIM;
    const int E = in_sizes[2];

    const int total4 = N * (DIM / 4);
    k_h2half<<<(total4 + 255) / 256, 256>>>((const float4*)h, total4);

    k_zero_deg<<<(N + 255) / 256, 256>>>(N);

    const int E4 = E / 4;
    if (E4 > 0)
        k_hist<<<(E4 + 255) / 256, 256>>>((const int4*)dst, E4);
    if (E4 * 4 < E)
        k_hist_tail<<<1, 256>>>(dst, E4 * 4, E);

    k_scan<<<1, 1024>>>(N);
    k_bucket<<<(E + 255) / 256, 256>>>(src, dst, e_w, E);
    k_agg<<<(N + 3) / 4, 256>>>(N);

    dim3 gemm_grid(DIM / GBN, (N + GBM - 1) / GBM);
    k_gemm_tf32<<<gemm_grid, 256>>>(weight, bias, out, N);
}

// round 13
// speedup vs baseline: 2.6097x; 1.1934x over previous
#include <cuda_runtime.h>
#include <cuda_fp16.h>
#include <cstdint>

// Problem shape (fixed by the dataset): N=50000 nodes, E=800000 edges, D=256.
#define DIM   256
#define MAXN  50176
#define MAXE  802816
#define SCAN_CHUNK 4096
#define MAXB  16            // max scan blocks: ceil(50000/4096)=13

// -------- scratch (static device globals: no runtime allocation) --------
__device__ int   g_deg[MAXN];
__device__ int   g_off[MAXN + 1];
__device__ int   g_cur[MAXN];
__device__ int   g_bsum[MAXB];
__device__ int   g_boff[MAXB];
__device__ __align__(16) int2   g_edge[MAXE];                 // bucketed (src, w_bits)
__device__ __align__(16) __half g_h16[(size_t)MAXN * DIM];    // fp16 copy of h
__device__ __align__(16) float  g_agg[(size_t)MAXN * DIM];    // rows >= N stay zero (GEMM padding)

// -------- 0. convert h to fp16 (one streaming pass) --------
__global__ void k_h2half(const float4* __restrict__ h4, int total4) {
    int i = blockIdx.x * blockDim.x + threadIdx.x;
    if (i < total4) {
        float4 v = h4[i];
        uint2 u;
        *reinterpret_cast<__half2*>(&u.x) = __floats2half2_rn(v.x, v.y);
        *reinterpret_cast<__half2*>(&u.y) = __floats2half2_rn(v.z, v.w);
        reinterpret_cast<uint2*>(g_h16)[i] = u;
    }
}

// -------- 1. zero degree counters --------
__global__ void k_zero_deg(int N) {
    int i = blockIdx.x * blockDim.x + threadIdx.x;
    if (i < N) g_deg[i] = 0;
}

// -------- 2. histogram of dst (int4-vectorized) --------
__global__ void k_hist(const int4* __restrict__ dst4, int E4) {
    int e = blockIdx.x * blockDim.x + threadIdx.x;
    if (e < E4) {
        int4 d = dst4[e];
        atomicAdd(&g_deg[d.x], 1);
        atomicAdd(&g_deg[d.y], 1);
        atomicAdd(&g_deg[d.z], 1);
        atomicAdd(&g_deg[d.w], 1);
    }
}
__global__ void k_hist_tail(const int* __restrict__ dst, int start, int E) {
    int e = start + blockIdx.x * blockDim.x + threadIdx.x;
    if (e < E) atomicAdd(&g_deg[dst[e]], 1);
}

// -------- 3a. per-block scan: each block handles 4096 elems, no serial loop --------
__global__ __launch_bounds__(1024)
void k_scan_blk(int N) {
    __shared__ int warp_sums[32];
    const int tid  = threadIdx.x;
    const int lane = tid & 31;
    const int warp = tid >> 5;
    const int i0   = blockIdx.x * SCAN_CHUNK + tid * 4;

    int v[4];
    #pragma unroll
    for (int j = 0; j < 4; j++) {
        int i = i0 + j;
        v[j] = (i < N) ? g_deg[i] : 0;
    }
    int tsum = v[0] + v[1] + v[2] + v[3];

    // inclusive warp scan of per-thread sums
    int x = tsum;
    #pragma unroll
    for (int d = 1; d < 32; d <<= 1) {
        int y = __shfl_up_sync(0xffffffffu, x, d);
        if (lane >= d) x += y;
    }
    if (lane == 31) warp_sums[warp] = x;
    __syncthreads();
    if (warp == 0) {
        int ws = warp_sums[lane];
        #pragma unroll
        for (int d = 1; d < 32; d <<= 1) {
            int y = __shfl_up_sync(0xffffffffu, ws, d);
            if (lane >= d) ws += y;
        }
        warp_sums[lane] = ws;
    }
    __syncthreads();

    int warp_off = (warp == 0) ? 0 : warp_sums[warp - 1];
    int excl = warp_off + (x - tsum);          // exclusive prefix within this block
    #pragma unroll
    for (int j = 0; j < 4; j++) {
        int i = i0 + j;
        if (i < N) g_off[i] = excl;
        excl += v[j];
    }
    if (tid == 0) g_bsum[blockIdx.x] = warp_sums[31];   // block total
}

// -------- 3b. scan of block sums (one warp) --------
__global__ void k_scan_top(int nb, int N) {
    const int lane = threadIdx.x;   // 32 threads
    int b = (lane < nb) ? g_bsum[lane] : 0;
    int x = b;
    #pragma unroll
    for (int d = 1; d < 32; d <<= 1) {
        int y = __shfl_up_sync(0xffffffffu, x, d);
        if (lane >= d) x += y;
    }
    if (lane < nb) g_boff[lane] = x - b;       // exclusive
    int total = __shfl_sync(0xffffffffu, x, 31);
    if (lane == 0) g_off[N] = total;
}

// -------- 3c. add block offsets, fill cursors --------
__global__ __launch_bounds__(1024)
void k_scan_add(int N) {
    int i = blockIdx.x * blockDim.x + threadIdx.x;
    if (i < N) {
        int off = g_off[i] + g_boff[i / SCAN_CHUNK];
        g_off[i] = off;
        g_cur[i] = off;
    }
}

// -------- 4. bucket packed (src, w_bits) by dst: ONE 8B scattered store/edge --------
__global__ void k_bucket(const int* __restrict__ src,
                         const int* __restrict__ dst,
                         const float* __restrict__ e_w, int E) {
    int e = blockIdx.x * blockDim.x + threadIdx.x;
    if (e < E) {
        int pos = atomicAdd(&g_cur[dst[e]], 1);
        g_edge[pos] = make_int2(src[e], __float_as_int(e_w[e]));
    }
}

// -------- 5. per-node aggregation on fp16 h: 4 nodes/block, 8B lanes, fp32 accum --------
__global__ __launch_bounds__(256)
void k_agg(int N) {
    const int t    = threadIdx.x;
    const int grp  = t >> 6;            // 0..3: node within block
    const int lane = t & 63;            // uint2 (4-feature) index within row
    const int n = blockIdx.x * 4 + grp;
    if (n >= N) return;

    const uint2* __restrict__ h16 = reinterpret_cast<const uint2*>(g_h16);

    int i         = g_off[n];
    const int end = g_off[n + 1];

    float4 acc = make_float4(0.f, 0.f, 0.f, 0.f);

    for (; i + 4 <= end; i += 4) {
        int2 e0 = g_edge[i], e1 = g_edge[i+1], e2 = g_edge[i+2], e3 = g_edge[i+3];
        float w0 = __int_as_float(e0.y), w1 = __int_as_float(e1.y);
        float w2 = __int_as_float(e2.y), w3 = __int_as_float(e3.y);
        uint2 u0 = __ldg(&h16[(size_t)e0.x * 64 + lane]);
        uint2 u1 = __ldg(&h16[(size_t)e1.x * 64 + lane]);
        uint2 u2 = __ldg(&h16[(size_t)e2.x * 64 + lane]);
        uint2 u3 = __ldg(&h16[(size_t)e3.x * 64 + lane]);
        {
            float2 a = __half22float2(*reinterpret_cast<const __half2*>(&u0.x));
            float2 b = __half22float2(*reinterpret_cast<const __half2*>(&u0.y));
            acc.x = fmaf(a.x, w0, acc.x); acc.y = fmaf(a.y, w0, acc.y);
            acc.z = fmaf(b.x, w0, acc.z); acc.w = fmaf(b.y, w0, acc.w);
        }
        {
            float2 a = __half22float2(*reinterpret_cast<const __half2*>(&u1.x));
            float2 b = __half22float2(*reinterpret_cast<const __half2*>(&u1.y));
            acc.x = fmaf(a.x, w1, acc.x); acc.y = fmaf(a.y, w1, acc.y);
            acc.z = fmaf(b.x, w1, acc.z); acc.w = fmaf(b.y, w1, acc.w);
        }
        {
            float2 a = __half22float2(*reinterpret_cast<const __half2*>(&u2.x));
            float2 b = __half22float2(*reinterpret_cast<const __half2*>(&u2.y));
            acc.x = fmaf(a.x, w2, acc.x); acc.y = fmaf(a.y, w2, acc.y);
            acc.z = fmaf(b.x, w2, acc.z); acc.w = fmaf(b.y, w2, acc.w);
        }
        {
            float2 a = __half22float2(*reinterpret_cast<const __half2*>(&u3.x));
            float2 b = __half22float2(*reinterpret_cast<const __half2*>(&u3.y));
            acc.x = fmaf(a.x, w3, acc.x); acc.y = fmaf(a.y, w3, acc.y);
            acc.z = fmaf(b.x, w3, acc.z); acc.w = fmaf(b.y, w3, acc.w);
        }
    }
    for (; i < end; i++) {
        int2 e = g_edge[i];
        float w = __int_as_float(e.y);
        uint2 u = __ldg(&h16[(size_t)e.x * 64 + lane]);
        float2 a = __half22float2(*reinterpret_cast<const __half2*>(&u.x));
        float2 b = __half22float2(*reinterpret_cast<const __half2*>(&u.y));
        acc.x = fmaf(a.x, w, acc.x); acc.y = fmaf(a.y, w, acc.y);
        acc.z = fmaf(b.x, w, acc.z); acc.w = fmaf(b.y, w, acc.w);
    }

    reinterpret_cast<float4*>(g_agg)[(size_t)n * 64 + lane] = acc;
}

// -------- 6. TF32 tensor-core GEMM with register-prefetch pipelining --------
#define GBM 128
#define GBN 64
#define GBK 32
#define A_PITCH 36
#define B_PITCH 72

__device__ __forceinline__ float to_tf32(float x) {
    float y;
    asm("cvt.rna.tf32.f32 %0, %1;" : "=f"(y) : "f"(x));
    return y;
}

__device__ __forceinline__ void mma_tf32(float& d0, float& d1, float& d2, float& d3,
                                         uint32_t a0, uint32_t a1, uint32_t a2, uint32_t a3,
                                         uint32_t b0, uint32_t b1) {
    asm volatile(
        "mma.sync.aligned.m16n8k8.row.col.f32.tf32.tf32.f32 "
        "{%0,%1,%2,%3}, {%4,%5,%6,%7}, {%8,%9}, {%0,%1,%2,%3};"
        : "+f"(d0), "+f"(d1), "+f"(d2), "+f"(d3)
        : "r"(a0), "r"(a1), "r"(a2), "r"(a3), "r"(b0), "r"(b1));
}

__global__ __launch_bounds__(256)
void k_gemm_tf32(const float* __restrict__ W,     // [256,256] row-major (k, n)
                 const float* __restrict__ bias,  // [256]
                 float* __restrict__ C, int M) {
    __shared__ float As[GBM * A_PITCH];
    __shared__ float Bs[GBK * B_PITCH];
    __shared__ float sBias[GBN];

    const int tid    = threadIdx.x;
    const int warp   = tid >> 5;
    const int lane   = tid & 31;
    const int gid    = lane >> 2;
    const int tig    = lane & 3;
    const int warp_m = warp >> 1;
    const int warp_n = warp & 1;
    const int wm0    = warp_m * 32;
    const int wn0    = warp_n * 32;
    const int tile_m = blockIdx.y * GBM;
    const int tile_n = blockIdx.x * GBN;
    const float* A   = g_agg;

    if (tid < GBN) sBias[tid] = bias[tile_n + tid];

    float acc[2][4][4];
    #pragma unroll
    for (int i = 0; i < 2; i++)
        #pragma unroll
        for (int j = 0; j < 4; j++)
            #pragma unroll
            for (int r = 0; r < 4; r++) acc[i][j][r] = 0.0f;

    const int a_row = tid >> 3;
    const int a_q   = tid & 7;
    const int b_row = tid >> 4;
    const int b_q   = tid & 15;

    float4 ra[4], rb[2];

    #pragma unroll
    for (int it = 0; it < 4; it++)
        ra[it] = *reinterpret_cast<const float4*>(
            &A[(size_t)(tile_m + a_row + it * 32) * DIM + a_q * 4]);
    #pragma unroll
    for (int it = 0; it < 2; it++)
        rb[it] = *reinterpret_cast<const float4*>(
            &W[(size_t)(b_row + it * 16) * DIM + tile_n + b_q * 4]);

    const int NK = DIM / GBK;   // 8
    for (int kt = 0; kt < NK; kt++) {
        #pragma unroll
        for (int it = 0; it < 4; it++) {
            float4 v = ra[it];
            v.x = to_tf32(v.x); v.y = to_tf32(v.y);
            v.z = to_tf32(v.z); v.w = to_tf32(v.w);
            *reinterpret_cast<float4*>(&As[(a_row + it * 32) * A_PITCH + a_q * 4]) = v;
        }
        #pragma unroll
        for (int it = 0; it < 2; it++) {
            float4 v = rb[it];
            v.x = to_tf32(v.x); v.y = to_tf32(v.y);
            v.z = to_tf32(v.z); v.w = to_tf32(v.w);
            *reinterpret_cast<float4*>(&Bs[(b_row + it * 16) * B_PITCH + b_q * 4]) = v;
        }
        __syncthreads();

        if (kt + 1 < NK) {
            const int k0 = (kt + 1) * GBK;
            #pragma unroll
            for (int it = 0; it < 4; it++)
                ra[it] = *reinterpret_cast<const float4*>(
                    &A[(size_t)(tile_m + a_row + it * 32) * DIM + k0 + a_q * 4]);
            #pragma unroll
            for (int it = 0; it < 2; it++)
                rb[it] = *reinterpret_cast<const float4*>(
                    &W[(size_t)(k0 + b_row + it * 16) * DIM + tile_n + b_q * 4]);
        }

        #pragma unroll
        for (int kk = 0; kk < GBK / 8; kk++) {
            const int kb = kk * 8;
            uint32_t a[2][4], b[4][2];
            #pragma unroll
            for (int mt = 0; mt < 2; mt++) {
                int m0 = wm0 + mt * 16;
                a[mt][0] = __float_as_uint(As[(m0 + gid)     * A_PITCH + kb + tig]);
                a[mt][1] = __float_as_uint(As[(m0 + 8 + gid) * A_PITCH + kb + tig]);
                a[mt][2] = __float_as_uint(As[(m0 + gid)     * A_PITCH + kb + tig + 4]);
                a[mt][3] = __float_as_uint(As[(m0 + 8 + gid) * A_PITCH + kb + tig + 4]);
            }
            #pragma unroll
            for (int nt = 0; nt < 4; nt++) {
                int n0 = wn0 + nt * 8 + gid;
                b[nt][0] = __float_as_uint(Bs[(kb + tig)     * B_PITCH + n0]);
                b[nt][1] = __float_as_uint(Bs[(kb + tig + 4) * B_PITCH + n0]);
            }
            #pragma unroll
            for (int mt = 0; mt < 2; mt++)
                #pragma unroll
                for (int nt = 0; nt < 4; nt++)
                    mma_tf32(acc[mt][nt][0], acc[mt][nt][1], acc[mt][nt][2], acc[mt][nt][3],
                             a[mt][0], a[mt][1], a[mt][2], a[mt][3],
                             b[nt][0], b[nt][1]);
        }
        __syncthreads();
    }

    #pragma unroll
    for (int mt = 0; mt < 2; mt++) {
        int r0 = tile_m + wm0 + mt * 16 + gid;
        int r1 = r0 + 8;
        #pragma unroll
        for (int nt = 0; nt < 4; nt++) {
            int cl = wn0 + nt * 8 + tig * 2;
            int gc = tile_n + cl;
            float b0 = sBias[cl], b1 = sBias[cl + 1];
            if (r0 < M) {
                float2 o; o.x = acc[mt][nt][0] + b0; o.y = acc[mt][nt][1] + b1;
                *reinterpret_cast<float2*>(&C[(size_t)r0 * DIM + gc]) = o;
            }
            if (r1 < M) {
                float2 o; o.x = acc[mt][nt][2] + b0; o.y = acc[mt][nt][3] + b1;
                *reinterpret_cast<float2*>(&C[(size_t)r1 * DIM + gc]) = o;
            }
        }
    }
}

extern "C" void kernel_launch(void* const* d_in, const int* in_sizes, int n_in,
                              void* d_out, int out_size) {
    const float* h      = (const float*)d_in[0];   // [N, 256]
    const float* e_w    = (const float*)d_in[1];   // [E, 1]
    const int*   src    = (const int*)  d_in[2];   // [E]
    const int*   dst    = (const int*)  d_in[3];   // [E]
    const float* weight = (const float*)d_in[4];   // [256, 256]
    const float* bias   = (const float*)d_in[5];   // [256]
    float* out = (float*)d_out;                    // [N, 256]

    const int N = in_sizes[0] / DIM;
    const int E = in_sizes[2];

    const int total4 = N * (DIM / 4);
    k_h2half<<<(total4 + 255) / 256, 256>>>((const float4*)h, total4);

    k_zero_deg<<<(N + 255) / 256, 256>>>(N);

    const int E4 = E / 4;
    if (E4 > 0)
        k_hist<<<(E4 + 255) / 256, 256>>>((const int4*)dst, E4);
    if (E4 * 4 < E)
        k_hist_tail<<<1, 256>>>(dst, E4 * 4, E);

    const int nb = (N + SCAN_CHUNK - 1) / SCAN_CHUNK;   // 13
    k_scan_blk<<<nb, 1024>>>(N);
    k_scan_top<<<1, 32>>>(nb, N);
    k_scan_add<<<(N + 1023) / 1024, 1024>>>(N);

    k_bucket<<<(E + 255) / 256, 256>>>(src, dst, e_w, E);
    k_agg<<<(N + 3) / 4, 256>>>(N);

    dim3 gemm_grid(DIM / GBN, (N + GBM - 1) / GBM);
    k_gemm_tf32<<<gemm_grid, 256>>>(weight, bias, out, N);
}

// round 14
// speedup vs baseline: 2.7116x; 1.0390x over previous
#include <cuda_runtime.h>
#include <cuda_fp16.h>
#include <cstdint>

// Problem shape (fixed by the dataset): N=50000 nodes, E=800000 edges, D=256.
#define DIM   256
#define MAXN  50176
#define MAXE  802816
#define SCAN_CHUNK 4096
#define MAXB  16            // max scan blocks: ceil(50000/4096)=13

// -------- scratch (static device globals: no runtime allocation) --------
__device__ int   g_deg[MAXN];
__device__ int   g_off[MAXN + 1];
__device__ int   g_cur[MAXN];
__device__ int   g_bsum[MAXB];
__device__ int   g_boff[MAXB];
__device__ __align__(16) int2   g_edge[MAXE];                 // bucketed (src, w_bits)
__device__ __align__(16) __half g_hw16[(size_t)MAXN * DIM];   // fp16 hW = h @ W

// -------- 1. zero degree counters --------
__global__ void k_zero_deg(int N) {
    int i = blockIdx.x * blockDim.x + threadIdx.x;
    if (i < N) g_deg[i] = 0;
}

// -------- 2. histogram of dst (int4-vectorized) --------
__global__ void k_hist(const int4* __restrict__ dst4, int E4) {
    int e = blockIdx.x * blockDim.x + threadIdx.x;
    if (e < E4) {
        int4 d = dst4[e];
        atomicAdd(&g_deg[d.x], 1);
        atomicAdd(&g_deg[d.y], 1);
        atomicAdd(&g_deg[d.z], 1);
        atomicAdd(&g_deg[d.w], 1);
    }
}
__global__ void k_hist_tail(const int* __restrict__ dst, int start, int E) {
    int e = start + blockIdx.x * blockDim.x + threadIdx.x;
    if (e < E) atomicAdd(&g_deg[dst[e]], 1);
}

// -------- 3a. per-block scan: each block handles 4096 elems --------
__global__ __launch_bounds__(1024)
void k_scan_blk(int N) {
    __shared__ int warp_sums[32];
    const int tid  = threadIdx.x;
    const int lane = tid & 31;
    const int warp = tid >> 5;
    const int i0   = blockIdx.x * SCAN_CHUNK + tid * 4;

    int v[4];
    #pragma unroll
    for (int j = 0; j < 4; j++) {
        int i = i0 + j;
        v[j] = (i < N) ? g_deg[i] : 0;
    }
    int tsum = v[0] + v[1] + v[2] + v[3];

    int x = tsum;
    #pragma unroll
    for (int d = 1; d < 32; d <<= 1) {
        int y = __shfl_up_sync(0xffffffffu, x, d);
        if (lane >= d) x += y;
    }
    if (lane == 31) warp_sums[warp] = x;
    __syncthreads();
    if (warp == 0) {
        int ws = warp_sums[lane];
        #pragma unroll
        for (int d = 1; d < 32; d <<= 1) {
            int y = __shfl_up_sync(0xffffffffu, ws, d);
            if (lane >= d) ws += y;
        }
        warp_sums[lane] = ws;
    }
    __syncthreads();

    int warp_off = (warp == 0) ? 0 : warp_sums[warp - 1];
    int excl = warp_off + (x - tsum);
    #pragma unroll
    for (int j = 0; j < 4; j++) {
        int i = i0 + j;
        if (i < N) g_off[i] = excl;
        excl += v[j];
    }
    if (tid == 0) g_bsum[blockIdx.x] = warp_sums[31];
}

// -------- 3b. scan of block sums (one warp) --------
__global__ void k_scan_top(int nb, int N) {
    const int lane = threadIdx.x;   // 32 threads
    int b = (lane < nb) ? g_bsum[lane] : 0;
    int x = b;
    #pragma unroll
    for (int d = 1; d < 32; d <<= 1) {
        int y = __shfl_up_sync(0xffffffffu, x, d);
        if (lane >= d) x += y;
    }
    if (lane < nb) g_boff[lane] = x - b;
    int total = __shfl_sync(0xffffffffu, x, 31);
    if (lane == 0) g_off[N] = total;
}

// -------- 3c. add block offsets, fill cursors --------
__global__ __launch_bounds__(1024)
void k_scan_add(int N) {
    int i = blockIdx.x * blockDim.x + threadIdx.x;
    if (i < N) {
        int off = g_off[i] + g_boff[i / SCAN_CHUNK];
        g_off[i] = off;
        g_cur[i] = off;
    }
}

// -------- 4. bucket packed (src, w_bits) by dst: 4 edges/thread for MLP --------
__global__ void k_bucket4(const int4* __restrict__ src4,
                          const int4* __restrict__ dst4,
                          const float4* __restrict__ ew4, int E4) {
    int e = blockIdx.x * blockDim.x + threadIdx.x;
    if (e < E4) {
        int4   s = src4[e];
        int4   d = dst4[e];
        float4 w = ew4[e];
        int p0 = atomicAdd(&g_cur[d.x], 1);
        int p1 = atomicAdd(&g_cur[d.y], 1);
        int p2 = atomicAdd(&g_cur[d.z], 1);
        int p3 = atomicAdd(&g_cur[d.w], 1);
        g_edge[p0] = make_int2(s.x, __float_as_int(w.x));
        g_edge[p1] = make_int2(s.y, __float_as_int(w.y));
        g_edge[p2] = make_int2(s.z, __float_as_int(w.z));
        g_edge[p3] = make_int2(s.w, __float_as_int(w.w));
    }
}
__global__ void k_bucket_tail(const int* __restrict__ src,
                              const int* __restrict__ dst,
                              const float* __restrict__ e_w, int start, int E) {
    int e = start + blockIdx.x * blockDim.x + threadIdx.x;
    if (e < E) {
        int pos = atomicAdd(&g_cur[dst[e]], 1);
        g_edge[pos] = make_int2(src[e], __float_as_int(e_w[e]));
    }
}

// -------- 5. TF32 GEMM first: hW16 = fp16(h @ W), register-prefetch pipelined --------
// 128x64 tile, BK=32, 256 threads (8 warps), warp = 32x32 (2x4 m16n8 tiles).
#define GBM 128
#define GBN 64
#define GBK 32
#define A_PITCH 36
#define B_PITCH 72

__device__ __forceinline__ float to_tf32(float x) {
    float y;
    asm("cvt.rna.tf32.f32 %0, %1;" : "=f"(y) : "f"(x));
    return y;
}

__device__ __forceinline__ void mma_tf32(float& d0, float& d1, float& d2, float& d3,
                                         uint32_t a0, uint32_t a1, uint32_t a2, uint32_t a3,
                                         uint32_t b0, uint32_t b1) {
    asm volatile(
        "mma.sync.aligned.m16n8k8.row.col.f32.tf32.tf32.f32 "
        "{%0,%1,%2,%3}, {%4,%5,%6,%7}, {%8,%9}, {%0,%1,%2,%3};"
        : "+f"(d0), "+f"(d1), "+f"(d2), "+f"(d3)
        : "r"(a0), "r"(a1), "r"(a2), "r"(a3), "r"(b0), "r"(b1));
}

__global__ __launch_bounds__(256)
void k_gemm_tf32(const float* __restrict__ A,     // h [M,256] (NOT padded: guard m)
                 const float* __restrict__ W,     // [256,256] row-major (k, n)
                 int M) {
    __shared__ float As[GBM * A_PITCH];
    __shared__ float Bs[GBK * B_PITCH];

    const int tid    = threadIdx.x;
    const int warp   = tid >> 5;
    const int lane   = tid & 31;
    const int gid    = lane >> 2;
    const int tig    = lane & 3;
    const int warp_m = warp >> 1;
    const int warp_n = warp & 1;
    const int wm0    = warp_m * 32;
    const int wn0    = warp_n * 32;
    const int tile_m = blockIdx.y * GBM;
    const int tile_n = blockIdx.x * GBN;

    float acc[2][4][4];
    #pragma unroll
    for (int i = 0; i < 2; i++)
        #pragma unroll
        for (int j = 0; j < 4; j++)
            #pragma unroll
            for (int r = 0; r < 4; r++) acc[i][j][r] = 0.0f;

    const int a_row = tid >> 3;
    const int a_q   = tid & 7;
    const int b_row = tid >> 4;
    const int b_q   = tid & 15;

    float4 ra[4], rb[2];

    #pragma unroll
    for (int it = 0; it < 4; it++) {
        int gm = tile_m + a_row + it * 32;
        ra[it] = (gm < M) ? *reinterpret_cast<const float4*>(&A[(size_t)gm * DIM + a_q * 4])
                          : make_float4(0.f, 0.f, 0.f, 0.f);
    }
    #pragma unroll
    for (int it = 0; it < 2; it++)
        rb[it] = *reinterpret_cast<const float4*>(
            &W[(size_t)(b_row + it * 16) * DIM + tile_n + b_q * 4]);

    const int NK = DIM / GBK;   // 8
    for (int kt = 0; kt < NK; kt++) {
        #pragma unroll
        for (int it = 0; it < 4; it++) {
            float4 v = ra[it];
            v.x = to_tf32(v.x); v.y = to_tf32(v.y);
            v.z = to_tf32(v.z); v.w = to_tf32(v.w);
            *reinterpret_cast<float4*>(&As[(a_row + it * 32) * A_PITCH + a_q * 4]) = v;
        }
        #pragma unroll
        for (int it = 0; it < 2; it++) {
            float4 v = rb[it];
            v.x = to_tf32(v.x); v.y = to_tf32(v.y);
            v.z = to_tf32(v.z); v.w = to_tf32(v.w);
            *reinterpret_cast<float4*>(&Bs[(b_row + it * 16) * B_PITCH + b_q * 4]) = v;
        }
        __syncthreads();

        if (kt + 1 < NK) {
            const int k0 = (kt + 1) * GBK;
            #pragma unroll
            for (int it = 0; it < 4; it++) {
                int gm = tile_m + a_row + it * 32;
                ra[it] = (gm < M) ? *reinterpret_cast<const float4*>(
                                        &A[(size_t)gm * DIM + k0 + a_q * 4])
                                  : make_float4(0.f, 0.f, 0.f, 0.f);
            }
            #pragma unroll
            for (int it = 0; it < 2; it++)
                rb[it] = *reinterpret_cast<const float4*>(
                    &W[(size_t)(k0 + b_row + it * 16) * DIM + tile_n + b_q * 4]);
        }

        #pragma unroll
        for (int kk = 0; kk < GBK / 8; kk++) {
            const int kb = kk * 8;
            uint32_t a[2][4], b[4][2];
            #pragma unroll
            for (int mt = 0; mt < 2; mt++) {
                int m0 = wm0 + mt * 16;
                a[mt][0] = __float_as_uint(As[(m0 + gid)     * A_PITCH + kb + tig]);
                a[mt][1] = __float_as_uint(As[(m0 + 8 + gid) * A_PITCH + kb + tig]);
                a[mt][2] = __float_as_uint(As[(m0 + gid)     * A_PITCH + kb + tig + 4]);
                a[mt][3] = __float_as_uint(As[(m0 + 8 + gid) * A_PITCH + kb + tig + 4]);
            }
            #pragma unroll
            for (int nt = 0; nt < 4; nt++) {
                int n0 = wn0 + nt * 8 + gid;
                b[nt][0] = __float_as_uint(Bs[(kb + tig)     * B_PITCH + n0]);
                b[nt][1] = __float_as_uint(Bs[(kb + tig + 4) * B_PITCH + n0]);
            }
            #pragma unroll
            for (int mt = 0; mt < 2; mt++)
                #pragma unroll
                for (int nt = 0; nt < 4; nt++)
                    mma_tf32(acc[mt][nt][0], acc[mt][nt][1], acc[mt][nt][2], acc[mt][nt][3],
                             a[mt][0], a[mt][1], a[mt][2], a[mt][3],
                             b[nt][0], b[nt][1]);
        }
        __syncthreads();
    }

    // ---- epilogue: store fp16 (no bias here; bias is added post-aggregation) ----
    #pragma unroll
    for (int mt = 0; mt < 2; mt++) {
        int r0 = tile_m + wm0 + mt * 16 + gid;
        int r1 = r0 + 8;
        #pragma unroll
        for (int nt = 0; nt < 4; nt++) {
            int gc = tile_n + wn0 + nt * 8 + tig * 2;
            if (r0 < M) {
                __half2 o = __floats2half2_rn(acc[mt][nt][0], acc[mt][nt][1]);
                *reinterpret_cast<__half2*>(&g_hw16[(size_t)r0 * DIM + gc]) = o;
            }
            if (r1 < M) {
                __half2 o = __floats2half2_rn(acc[mt][nt][2], acc[mt][nt][3]);
                *reinterpret_cast<__half2*>(&g_hw16[(size_t)r1 * DIM + gc]) = o;
            }
        }
    }
}

// -------- 6. aggregation over hW16, bias fused, writes d_out directly --------
__global__ __launch_bounds__(256)
void k_agg(const float* __restrict__ bias, float* __restrict__ out, int N) {
    const int t    = threadIdx.x;
    const int grp  = t >> 6;            // 0..3: node within block
    const int lane = t & 63;            // uint2 (4-feature) index within row
    const int n = blockIdx.x * 4 + grp;
    if (n >= N) return;

    const uint2* __restrict__ hw = reinterpret_cast<const uint2*>(g_hw16);

    int i         = g_off[n];
    const int end = g_off[n + 1];

    float4 bv = *reinterpret_cast<const float4*>(&bias[lane * 4]);
    float4 acc = make_float4(0.f, 0.f, 0.f, 0.f);

    for (; i + 4 <= end; i += 4) {
        int2 e0 = g_edge[i], e1 = g_edge[i+1], e2 = g_edge[i+2], e3 = g_edge[i+3];
        float w0 = __int_as_float(e0.y), w1 = __int_as_float(e1.y);
        float w2 = __int_as_float(e2.y), w3 = __int_as_float(e3.y);
        uint2 u0 = __ldg(&hw[(size_t)e0.x * 64 + lane]);
        uint2 u1 = __ldg(&hw[(size_t)e1.x * 64 + lane]);
        uint2 u2 = __ldg(&hw[(size_t)e2.x * 64 + lane]);
        uint2 u3 = __ldg(&hw[(size_t)e3.x * 64 + lane]);
        {
            float2 a = __half22float2(*reinterpret_cast<const __half2*>(&u0.x));
            float2 b = __half22float2(*reinterpret_cast<const __half2*>(&u0.y));
            acc.x = fmaf(a.x, w0, acc.x); acc.y = fmaf(a.y, w0, acc.y);
            acc.z = fmaf(b.x, w0, acc.z); acc.w = fmaf(b.y, w0, acc.w);
        }
        {
            float2 a = __half22float2(*reinterpret_cast<const __half2*>(&u1.x));
            float2 b = __half22float2(*reinterpret_cast<const __half2*>(&u1.y));
            acc.x = fmaf(a.x, w1, acc.x); acc.y = fmaf(a.y, w1, acc.y);
            acc.z = fmaf(b.x, w1, acc.z); acc.w = fmaf(b.y, w1, acc.w);
        }
        {
            float2 a = __half22float2(*reinterpret_cast<const __half2*>(&u2.x));
            float2 b = __half22float2(*reinterpret_cast<const __half2*>(&u2.y));
            acc.x = fmaf(a.x, w2, acc.x); acc.y = fmaf(a.y, w2, acc.y);
            acc.z = fmaf(b.x, w2, acc.z); acc.w = fmaf(b.y, w2, acc.w);
        }
        {
            float2 a = __half22float2(*reinterpret_cast<const __half2*>(&u3.x));
            float2 b = __half22float2(*reinterpret_cast<const __half2*>(&u3.y));
            acc.x = fmaf(a.x, w3, acc.x); acc.y = fmaf(a.y, w3, acc.y);
            acc.z = fmaf(b.x, w3, acc.z); acc.w = fmaf(b.y, w3, acc.w);
        }
    }
    for (; i < end; i++) {
        int2 e = g_edge[i];
        float w = __int_as_float(e.y);
        uint2 u = __ldg(&hw[(size_t)e.x * 64 + lane]);
        float2 a = __half22float2(*reinterpret_cast<const __half2*>(&u.x));
        float2 b = __half22float2(*reinterpret_cast<const __half2*>(&u.y));
        acc.x = fmaf(a.x, w, acc.x); acc.y = fmaf(a.y, w, acc.y);
        acc.z = fmaf(b.x, w, acc.z); acc.w = fmaf(b.y, w, acc.w);
    }

    acc.x += bv.x; acc.y += bv.y; acc.z += bv.z; acc.w += bv.w;
    reinterpret_cast<float4*>(out)[(size_t)n * 64 + lane] = acc;
}

extern "C" void kernel_launch(void* const* d_in, const int* in_sizes, int n_in,
                              void* d_out, int out_size) {
    const float* h      = (const float*)d_in[0];   // [N, 256]
    const float* e_w    = (const float*)d_in[1];   // [E, 1]
    const int*   src    = (const int*)  d_in[2];   // [E]
    const int*   dst    = (const int*)  d_in[3];   // [E]
    const float* weight = (const float*)d_in[4];   // [256, 256]
    const float* bias   = (const float*)d_in[5];   // [256]
    float* out = (float*)d_out;                    // [N, 256]

    const int N = in_sizes[0] / DIM;
    const int E = in_sizes[2];

    k_zero_deg<<<(N + 255) / 256, 256>>>(N);

    const int E4 = E / 4;
    if (E4 > 0)
        k_hist<<<(E4 + 255) / 256, 256>>>((const int4*)dst, E4);
    if (E4 * 4 < E)
        k_hist_tail<<<1, 256>>>(dst, E4 * 4, E);

    const int nb = (N + SCAN_CHUNK - 1) / SCAN_CHUNK;   // 13
    k_scan_blk<<<nb, 1024>>>(N);
    k_scan_top<<<1, 32>>>(nb, N);
    k_scan_add<<<(N + 1023) / 1024, 1024>>>(N);

    if (E4 > 0)
        k_bucket4<<<(E4 + 255) / 256, 256>>>((const int4*)src, (const int4*)dst,
                                             (const float4*)e_w, E4);
    if (E4 * 4 < E)
        k_bucket_tail<<<1, 256>>>(src, dst, e_w, E4 * 4, E);

    // GEMM first: hW16 = fp16(h @ W)  (independent of the bucketing chain)
    dim3 gemm_grid(DIM / GBN, (N + GBM - 1) / GBM);
    k_gemm_tf32<<<gemm_grid, 256>>>(h, weight, N);

    // Aggregate over hW16, fuse bias, write output
    k_agg<<<(N + 3) / 4, 256>>>(bias, out, N);
}

// round 16
// speedup vs baseline: 2.9172x; 1.0758x over previous
#include <cuda_runtime.h>
#include <cuda_fp16.h>
#include <cstdint>

// Problem shape (fixed by the dataset): N=50000 nodes, E=800000 edges, D=256.
#define DIM   256
#define MAXN  50176
#define MAXE  802816
#define SCAN_CHUNK 4096
#define MAXB  16            // max scan blocks: ceil(50000/4096)=13

// -------- scratch (static device globals: no runtime allocation) --------
__device__ int   g_deg[MAXN];      // statically zero; every call leaves it zero
__device__ int   g_off[MAXN + 1];
__device__ int   g_cur[MAXN];
__device__ int   g_bsum[MAXB];
__device__ __align__(16) int2   g_edge[MAXE];                 // bucketed (src, w_bits)
__device__ __align__(16) __half g_hw16[(size_t)MAXN * DIM];   // fp16 hW = h @ W

// -------- 1. histogram of dst (int4-vectorized); g_deg is zero on entry --------
__global__ void k_hist(const int4* __restrict__ dst4, int E4) {
    int e = blockIdx.x * blockDim.x + threadIdx.x;
    if (e < E4) {
        int4 d = dst4[e];
        atomicAdd(&g_deg[d.x], 1);
        atomicAdd(&g_deg[d.y], 1);
        atomicAdd(&g_deg[d.z], 1);
        atomicAdd(&g_deg[d.w], 1);
    }
}
__global__ void k_hist_tail(const int* __restrict__ dst, int start, int E) {
    int e = start + blockIdx.x * blockDim.x + threadIdx.x;
    if (e < E) atomicAdd(&g_deg[dst[e]], 1);
}

// -------- 2a. per-block scan (4096 elems/block); ALSO resets g_deg to zero --------
__global__ __launch_bounds__(1024)
void k_scan_blk(int N) {
    __shared__ int warp_sums[32];
    const int tid  = threadIdx.x;
    const int lane = tid & 31;
    const int warp = tid >> 5;
    const int i0   = blockIdx.x * SCAN_CHUNK + tid * 4;

    int v[4];
    #pragma unroll
    for (int j = 0; j < 4; j++) {
        int i = i0 + j;
        v[j] = (i < N) ? g_deg[i] : 0;
        if (i < N) g_deg[i] = 0;          // leave counters zeroed for the next call
    }
    int tsum = v[0] + v[1] + v[2] + v[3];

    int x = tsum;
    #pragma unroll
    for (int d = 1; d < 32; d <<= 1) {
        int y = __shfl_up_sync(0xffffffffu, x, d);
        if (lane >= d) x += y;
    }
    if (lane == 31) warp_sums[warp] = x;
    __syncthreads();
    if (warp == 0) {
        int ws = warp_sums[lane];
        #pragma unroll
        for (int d = 1; d < 32; d <<= 1) {
            int y = __shfl_up_sync(0xffffffffu, ws, d);
            if (lane >= d) ws += y;
        }
        warp_sums[lane] = ws;
    }
    __syncthreads();

    int warp_off = (warp == 0) ? 0 : warp_sums[warp - 1];
    int excl = warp_off + (x - tsum);
    #pragma unroll
    for (int j = 0; j < 4; j++) {
        int i = i0 + j;
        if (i < N) g_off[i] = excl;
        excl += v[j];
    }
    if (tid == 0) g_bsum[blockIdx.x] = warp_sums[31];
}

// -------- 2b. add block offsets (top-level 13-elem scan done redundantly per block) --------
__global__ __launch_bounds__(1024)
void k_scan_add(int nb, int N) {
    __shared__ int s_boff[MAXB];
    __shared__ int s_total;

    if (threadIdx.x < 32) {
        const int lane = threadIdx.x;
        int b = (lane < nb) ? g_bsum[lane] : 0;
        int x = b;
        #pragma unroll
        for (int d = 1; d < 32; d <<= 1) {
            int y = __shfl_up_sync(0xffffffffu, x, d);
            if (lane >= d) x += y;
        }
        if (lane < nb) s_boff[lane] = x - b;     // exclusive
        if (lane == 31) s_total = x;
    }
    __syncthreads();

    int i = blockIdx.x * blockDim.x + threadIdx.x;
    if (i < N) {
        int off = g_off[i] + s_boff[i / SCAN_CHUNK];
        g_off[i] = off;
        g_cur[i] = off;
    }
    if (blockIdx.x == 0 && threadIdx.x == 0) g_off[N] = s_total;
}

// -------- 3. bucket packed (src, w_bits) by dst: 4 edges/thread for MLP --------
__global__ void k_bucket4(const int4* __restrict__ src4,
                          const int4* __restrict__ dst4,
                          const float4* __restrict__ ew4, int E4) {
    int e = blockIdx.x * blockDim.x + threadIdx.x;
    if (e < E4) {
        int4   s = src4[e];
        int4   d = dst4[e];
        float4 w = ew4[e];
        int p0 = atomicAdd(&g_cur[d.x], 1);
        int p1 = atomicAdd(&g_cur[d.y], 1);
        int p2 = atomicAdd(&g_cur[d.z], 1);
        int p3 = atomicAdd(&g_cur[d.w], 1);
        g_edge[p0] = make_int2(s.x, __float_as_int(w.x));
        g_edge[p1] = make_int2(s.y, __float_as_int(w.y));
        g_edge[p2] = make_int2(s.z, __float_as_int(w.z));
        g_edge[p3] = make_int2(s.w, __float_as_int(w.w));
    }
}
__global__ void k_bucket_tail(const int* __restrict__ src,
                              const int* __restrict__ dst,
                              const float* __restrict__ e_w, int start, int E) {
    int e = start + blockIdx.x * blockDim.x + threadIdx.x;
    if (e < E) {
        int pos = atomicAdd(&g_cur[dst[e]], 1);
        g_edge[pos] = make_int2(src[e], __float_as_int(e_w[e]));
    }
}

// -------- 4. TF32 GEMM first: hW16 = fp16(h @ W), register-prefetch pipelined --------
#define GBM 128
#define GBN 64
#define GBK 32
#define A_PITCH 36
#define B_PITCH 72

__device__ __forceinline__ float to_tf32(float x) {
    float y;
    asm("cvt.rna.tf32.f32 %0, %1;" : "=f"(y) : "f"(x));
    return y;
}

__device__ __forceinline__ void mma_tf32(float& d0, float& d1, float& d2, float& d3,
                                         uint32_t a0, uint32_t a1, uint32_t a2, uint32_t a3,
                                         uint32_t b0, uint32_t b1) {
    asm volatile(
        "mma.sync.aligned.m16n8k8.row.col.f32.tf32.tf32.f32 "
        "{%0,%1,%2,%3}, {%4,%5,%6,%7}, {%8,%9}, {%0,%1,%2,%3};"
        : "+f"(d0), "+f"(d1), "+f"(d2), "+f"(d3)
        : "r"(a0), "r"(a1), "r"(a2), "r"(a3), "r"(b0), "r"(b1));
}

__global__ __launch_bounds__(256)
void k_gemm_tf32(const float* __restrict__ A,     // h [M,256] (NOT padded: guard m)
                 const float* __restrict__ W,     // [256,256] row-major (k, n)
                 int M) {
    __shared__ float As[GBM * A_PITCH];
    __shared__ float Bs[GBK * B_PITCH];

    const int tid    = threadIdx.x;
    const int warp   = tid >> 5;
    const int lane   = tid & 31;
    const int gid    = lane >> 2;
    const int tig    = lane & 3;
    const int warp_m = warp >> 1;
    const int warp_n = warp & 1;
    const int wm0    = warp_m * 32;
    const int wn0    = warp_n * 32;
    const int tile_m = blockIdx.y * GBM;
    const int tile_n = blockIdx.x * GBN;

    float acc[2][4][4];
    #pragma unroll
    for (int i = 0; i < 2; i++)
        #pragma unroll
        for (int j = 0; j < 4; j++)
            #pragma unroll
            for (int r = 0; r < 4; r++) acc[i][j][r] = 0.0f;

    const int a_row = tid >> 3;
    const int a_q   = tid & 7;
    const int b_row = tid >> 4;
    const int b_q   = tid & 15;

    float4 ra[4], rb[2];

    #pragma unroll
    for (int it = 0; it < 4; it++) {
        int gm = tile_m + a_row + it * 32;
        ra[it] = (gm < M) ? *reinterpret_cast<const float4*>(&A[(size_t)gm * DIM + a_q * 4])
                          : make_float4(0.f, 0.f, 0.f, 0.f);
    }
    #pragma unroll
    for (int it = 0; it < 2; it++)
        rb[it] = *reinterpret_cast<const float4*>(
            &W[(size_t)(b_row + it * 16) * DIM + tile_n + b_q * 4]);

    const int NK = DIM / GBK;   // 8
    for (int kt = 0; kt < NK; kt++) {
        #pragma unroll
        for (int it = 0; it < 4; it++) {
            float4 v = ra[it];
            v.x = to_tf32(v.x); v.y = to_tf32(v.y);
            v.z = to_tf32(v.z); v.w = to_tf32(v.w);
            *reinterpret_cast<float4*>(&As[(a_row + it * 32) * A_PITCH + a_q * 4]) = v;
        }
        #pragma unroll
        for (int it = 0; it < 2; it++) {
            float4 v = rb[it];
            v.x = to_tf32(v.x); v.y = to_tf32(v.y);
            v.z = to_tf32(v.z); v.w = to_tf32(v.w);
            *reinterpret_cast<float4*>(&Bs[(b_row + it * 16) * B_PITCH + b_q * 4]) = v;
        }
        __syncthreads();

        if (kt + 1 < NK) {
            const int k0 = (kt + 1) * GBK;
            #pragma unroll
            for (int it = 0; it < 4; it++) {
                int gm = tile_m + a_row + it * 32;
                ra[it] = (gm < M) ? *reinterpret_cast<const float4*>(
                                        &A[(size_t)gm * DIM + k0 + a_q * 4])
                                  : make_float4(0.f, 0.f, 0.f, 0.f);
            }
            #pragma unroll
            for (int it = 0; it < 2; it++)
                rb[it] = *reinterpret_cast<const float4*>(
                    &W[(size_t)(k0 + b_row + it * 16) * DIM + tile_n + b_q * 4]);
        }

        #pragma unroll
        for (int kk = 0; kk < GBK / 8; kk++) {
            const int kb = kk * 8;
            uint32_t a[2][4], b[4][2];
            #pragma unroll
            for (int mt = 0; mt < 2; mt++) {
                int m0 = wm0 + mt * 16;
                a[mt][0] = __float_as_uint(As[(m0 + gid)     * A_PITCH + kb + tig]);
                a[mt][1] = __float_as_uint(As[(m0 + 8 + gid) * A_PITCH + kb + tig]);
                a[mt][2] = __float_as_uint(As[(m0 + gid)     * A_PITCH + kb + tig + 4]);
                a[mt][3] = __float_as_uint(As[(m0 + 8 + gid) * A_PITCH + kb + tig + 4]);
            }
            #pragma unroll
            for (int nt = 0; nt < 4; nt++) {
                int n0 = wn0 + nt * 8 + gid;
                b[nt][0] = __float_as_uint(Bs[(kb + tig)     * B_PITCH + n0]);
                b[nt][1] = __float_as_uint(Bs[(kb + tig + 4) * B_PITCH + n0]);
            }
            #pragma unroll
            for (int mt = 0; mt < 2; mt++)
                #pragma unroll
                for (int nt = 0; nt < 4; nt++)
                    mma_tf32(acc[mt][nt][0], acc[mt][nt][1], acc[mt][nt][2], acc[mt][nt][3],
                             a[mt][0], a[mt][1], a[mt][2], a[mt][3],
                             b[nt][0], b[nt][1]);
        }
        __syncthreads();
    }

    // ---- epilogue: store fp16 (bias is added post-aggregation) ----
    #pragma unroll
    for (int mt = 0; mt < 2; mt++) {
        int r0 = tile_m + wm0 + mt * 16 + gid;
        int r1 = r0 + 8;
        #pragma unroll
        for (int nt = 0; nt < 4; nt++) {
            int gc = tile_n + wn0 + nt * 8 + tig * 2;
            if (r0 < M) {
                __half2 o = __floats2half2_rn(acc[mt][nt][0], acc[mt][nt][1]);
                *reinterpret_cast<__half2*>(&g_hw16[(size_t)r0 * DIM + gc]) = o;
            }
            if (r1 < M) {
                __half2 o = __floats2half2_rn(acc[mt][nt][2], acc[mt][nt][3]);
                *reinterpret_cast<__half2*>(&g_hw16[(size_t)r1 * DIM + gc]) = o;
            }
        }
    }
}

// -------- 5. aggregation over hW16: 8 nodes/block, 32 threads/node, uint4 lanes --------
__device__ __forceinline__ void acc_edge(const uint4& u, float ew,
                                         float4& acc0, float4& acc1) {
    float2 p0 = __half22float2(*reinterpret_cast<const __half2*>(&u.x));
    float2 p1 = __half22float2(*reinterpret_cast<const __half2*>(&u.y));
    float2 p2 = __half22float2(*reinterpret_cast<const __half2*>(&u.z));
    float2 p3 = __half22float2(*reinterpret_cast<const __half2*>(&u.w));
    acc0.x = fmaf(p0.x, ew, acc0.x); acc0.y = fmaf(p0.y, ew, acc0.y);
    acc0.z = fmaf(p1.x, ew, acc0.z); acc0.w = fmaf(p1.y, ew, acc0.w);
    acc1.x = fmaf(p2.x, ew, acc1.x); acc1.y = fmaf(p2.y, ew, acc1.y);
    acc1.z = fmaf(p3.x, ew, acc1.z); acc1.w = fmaf(p3.y, ew, acc1.w);
}

__global__ __launch_bounds__(256)
void k_agg(const float* __restrict__ bias, float* __restrict__ out, int N) {
    const int t    = threadIdx.x;
    const int grp  = t >> 5;            // 0..7: node within block
    const int lane = t & 31;            // uint4 (8-feature) index within row
    const int n = blockIdx.x * 8 + grp;
    if (n >= N) return;

    const uint4* __restrict__ hw = reinterpret_cast<const uint4*>(g_hw16);  // row = 32 uint4

    int i         = g_off[n];
    const int end = g_off[n + 1];

    float4 acc0 = make_float4(0.f, 0.f, 0.f, 0.f);
    float4 acc1 = make_float4(0.f, 0.f, 0.f, 0.f);

    for (; i + 4 <= end; i += 4) {
        int2 e0 = g_edge[i], e1 = g_edge[i+1], e2 = g_edge[i+2], e3 = g_edge[i+3];
        float w0 = __int_as_float(e0.y), w1 = __int_as_float(e1.y);
        float w2 = __int_as_float(e2.y), w3 = __int_as_float(e3.y);
        uint4 u0 = __ldg(&hw[(size_t)e0.x * 32 + lane]);
        uint4 u1 = __ldg(&hw[(size_t)e1.x * 32 + lane]);
        uint4 u2 = __ldg(&hw[(size_t)e2.x * 32 + lane]);
        uint4 u3 = __ldg(&hw[(size_t)e3.x * 32 + lane]);
        acc_edge(u0, w0, acc0, acc1);
        acc_edge(u1, w1, acc0, acc1);
        acc_edge(u2, w2, acc0, acc1);
        acc_edge(u3, w3, acc0, acc1);
    }
    for (; i < end; i++) {
        int2 e = g_edge[i];
        float ew = __int_as_float(e.y);
        uint4 u = __ldg(&hw[(size_t)e.x * 32 + lane]);
        acc_edge(u, ew, acc0, acc1);
    }

    float4 bv0 = *reinterpret_cast<const float4*>(&bias[lane * 8]);
    float4 bv1 = *reinterpret_cast<const float4*>(&bias[lane * 8 + 4]);
    acc0.x += bv0.x; acc0.y += bv0.y; acc0.z += bv0.z; acc0.w += bv0.w;
    acc1.x += bv1.x; acc1.y += bv1.y; acc1.z += bv1.z; acc1.w += bv1.w;

    float4* orow = reinterpret_cast<float4*>(out) + (size_t)n * 64 + lane * 2;
    orow[0] = acc0;
    orow[1] = acc1;
}

extern "C" void kernel_launch(void* const* d_in, const int* in_sizes, int n_in,
                              void* d_out, int out_size) {
    const float* h      = (const float*)d_in[0];   // [N, 256]
    const float* e_w    = (const float*)d_in[1];   // [E, 1]
    const int*   src    = (const int*)  d_in[2];   // [E]
    const int*   dst    = (const int*)  d_in[3];   // [E]
    const float* weight = (const float*)d_in[4];   // [256, 256]
    const float* bias   = (const float*)d_in[5];   // [256]
    float* out = (float*)d_out;                    // [N, 256]

    const int N = in_sizes[0] / DIM;
    const int E = in_sizes[2];

    const int E4 = E / 4;
    if (E4 > 0)
        k_hist<<<(E4 + 255) / 256, 256>>>((const int4*)dst, E4);
    if (E4 * 4 < E)
        k_hist_tail<<<1, 256>>>(dst, E4 * 4, E);

    const int nb = (N + SCAN_CHUNK - 1) / SCAN_CHUNK;   // 13
    k_scan_blk<<<nb, 1024>>>(N);                        // also re-zeros g_deg
    k_scan_add<<<(N + 1023) / 1024, 1024>>>(nb, N);     // top-scan fused in

    if (E4 > 0)
        k_bucket4<<<(E4 + 255) / 256, 256>>>((const int4*)src, (const int4*)dst,
                                             (const float4*)e_w, E4);
    if (E4 * 4 < E)
        k_bucket_tail<<<1, 256>>>(src, dst, e_w, E4 * 4, E);

    // GEMM: hW16 = fp16(h @ W)  (independent of the bucketing chain)
    dim3 gemm_grid(DIM / GBN, (N + GBM - 1) / GBM);
    k_gemm_tf32<<<gemm_grid, 256>>>(h, weight, N);

    // Aggregate over hW16, fuse bias, write output
    k_agg<<<(N + 7) / 8, 256>>>(bias, out, N);
}